// round 13
// baseline (speedup 1.0000x reference)
#include <cuda_runtime.h>
#include <math.h>
#include <stdint.h>

// ---------------- problem constants ----------------
#define DM      4096
#define MROWS   8192          // B*N = 4*2048
#define IB      1024          // block size (DM / 4 blocks)
#define DFF     5461
#define EPSD    1e-5

// ---------------- scratch (device globals; no allocations allowed) ----------
__device__ float  g_xa[(size_t)MROWS * DM];        // 128 MB silu(x)
__device__ float  g_pre[4ULL * MROWS * DM];        // 512 MB gate pre-activations
__device__ float  g_lnct[(size_t)MROWS * DM];      // 128 MB LN(i*z) values
__device__ float  g_lni[(size_t)MROWS * DM];       // 128 MB LN(i) values
__device__ float  g_obuf[(size_t)MROWS * DM];      // 128 MB o-gate values
__device__ float  g_ratio[DM];                     // ct/nt (fp32, ref-matched)
__device__ double g_htmsum[DM];
__device__ double g_s[DM];                         // slstm_out
__device__ double g_v[DFF];                        // left*right (pre-LN)
__device__ double g_u[DFF];                        // LN'd

// ---------------- XLA-matched elementwise math ----------------
__device__ __forceinline__ float tanh_xla(float x) {
    const float kMax = 7.90531110763549805f;
    float cx = fminf(fmaxf(x, -kMax), kMax);
    float x2 = __fmul_rn(cx, cx);
    float p = fmaf(x2, -2.76076847742355e-16f, 2.00018790482477e-13f);
    p = fmaf(p, x2, -8.60467152213735e-11f);
    p = fmaf(p, x2, 5.12229709037114e-08f);
    p = fmaf(p, x2, 1.48572235717979e-05f);
    p = fmaf(p, x2, 6.37261928875436e-04f);
    p = fmaf(p, x2, 4.89352455891786e-03f);
    p = __fmul_rn(cx, p);
    float q = fmaf(x2, 1.19825839466702e-06f, 1.18534705686654e-04f);
    q = fmaf(q, x2, 2.26843463243900e-03f);
    q = fmaf(q, x2, 4.89352518554385e-03f);
    float r = __fdiv_rn(p, q);
    return (fabsf(x) < 0.0004f) ? x : r;
}

__device__ __forceinline__ float logistic_xla(float x) {
    return fmaf(0.5f, tanh_xla(__fmul_rn(0.5f, x)), 0.5f);
}

__device__ __forceinline__ float silu_xla(float x) {
    return __fmul_rn(x, logistic_xla(x));
}

// ---------------- TF32 helpers ----------------
__device__ __forceinline__ float to_tf32(float v) {
    unsigned u;
    asm("cvt.rna.tf32.f32 %0, %1;" : "=r"(u) : "f"(v));
    return __uint_as_float(u);
}

__device__ __forceinline__ void mma_tf32(float4& d, const float* a, float b0, float b1) {
    asm volatile(
        "mma.sync.aligned.m16n8k8.row.col.f32.tf32.tf32.f32 "
        "{%0,%1,%2,%3}, {%4,%5,%6,%7}, {%8,%9}, {%0,%1,%2,%3};\n"
        : "+f"(d.x), "+f"(d.y), "+f"(d.z), "+f"(d.w)
        : "r"(__float_as_uint(a[0])), "r"(__float_as_uint(a[1])),
          "r"(__float_as_uint(a[2])), "r"(__float_as_uint(a[3])),
          "r"(__float_as_uint(b0)), "r"(__float_as_uint(b1)));
}

// ---------------- fp64 block reduce ----------------
template <int NV>
__device__ __forceinline__ void block_reduce_d(double* v, double* sred) {
    const int lane = threadIdx.x & 31;
    const int wid  = threadIdx.x >> 5;
    const int nw   = (blockDim.x + 31) >> 5;
#pragma unroll
    for (int i = 0; i < NV; ++i) {
        double x = v[i];
#pragma unroll
        for (int o = 16; o > 0; o >>= 1) x += __shfl_xor_sync(0xffffffffu, x, o);
        v[i] = x;
    }
    __syncthreads();
    if (lane == 0) {
#pragma unroll
        for (int i = 0; i < NV; ++i) sred[wid * NV + i] = v[i];
    }
    __syncthreads();
    if (wid == 0) {
#pragma unroll
        for (int i = 0; i < NV; ++i) {
            double x = (lane < nw) ? sred[lane * NV + i] : 0.0;
#pragma unroll
            for (int o = 16; o > 0; o >>= 1) x += __shfl_xor_sync(0xffffffffu, x, o);
            if (lane == 0) sred[i] = x;
        }
    }
    __syncthreads();
#pragma unroll
    for (int i = 0; i < NV; ++i) v[i] = sred[i];
    __syncthreads();
}

// ---------------- kernel: zero + silu ----------------
__global__ void k_zero() {
    int idx = blockIdx.x * blockDim.x + threadIdx.x;
    if (idx < DM) g_htmsum[idx] = 0.0;
}

__global__ __launch_bounds__(256) void k_silu(const float* __restrict__ x) {
    size_t i = ((size_t)blockIdx.x * 256 + threadIdx.x) * 4;
    float4 v = *(const float4*)(x + i);
    v.x = silu_xla(v.x); v.y = silu_xla(v.y); v.z = silu_xla(v.z); v.w = silu_xla(v.w);
    *(float4*)(g_xa + i) = v;
}

// ---------------- kernel: scalar fp32 SGEMM (gates i,f), ascending-k -------
// Bit-exact match of XLA's sgemm chains (amplified denominator path).
__global__ __launch_bounds__(256, 2) void k_gemm_if(const float* __restrict__ Wg) {
    __shared__ __align__(16) float As[2][16 * 132];
    __shared__ __align__(16) float Bs[2][16 * 132];

    const int mtile = blockIdx.x;
    const int ntile = blockIdx.y;
    const int g     = blockIdx.z & 1;        // gate 0 or 1
    const int blk   = blockIdx.z >> 1;

    const int tid = threadIdx.x;
    const int tx  = tid & 15;
    const int ty  = tid >> 4;
    const int rb  = ty * 8;
    const int nb1 = tx * 4;
    const int nb2 = 64 + tx * 4;

    const float* aBase = g_xa + (size_t)(mtile * 128) * DM + blk * IB;
    const float* bBase = Wg + ((size_t)(g * 4 + blk)) * IB * IB + (size_t)(ntile * 128) * IB;

    const int s0 = tid, s1 = tid + 256;
    const int ar0 = s0 >> 2, aq0 = (s0 & 3) * 4;
    const int ar1 = s1 >> 2, aq1 = (s1 & 3) * 4;

    float acc[8][8];
#pragma unroll
    for (int i = 0; i < 8; ++i)
#pragma unroll
        for (int j = 0; j < 8; ++j) acc[i][j] = 0.0f;

    float4 pa0, pa1, pb0, pb1;
    pa0 = *(const float4*)(aBase + (size_t)ar0 * DM + aq0);
    pa1 = *(const float4*)(aBase + (size_t)ar1 * DM + aq1);
    pb0 = *(const float4*)(bBase + (size_t)ar0 * IB + aq0);
    pb1 = *(const float4*)(bBase + (size_t)ar1 * IB + aq1);
    {
        float* A = As[0]; float* B = Bs[0];
        A[(aq0 + 0) * 132 + ar0] = pa0.x; A[(aq0 + 1) * 132 + ar0] = pa0.y;
        A[(aq0 + 2) * 132 + ar0] = pa0.z; A[(aq0 + 3) * 132 + ar0] = pa0.w;
        A[(aq1 + 0) * 132 + ar1] = pa1.x; A[(aq1 + 1) * 132 + ar1] = pa1.y;
        A[(aq1 + 2) * 132 + ar1] = pa1.z; A[(aq1 + 3) * 132 + ar1] = pa1.w;
        B[(aq0 + 0) * 132 + ar0] = pb0.x; B[(aq0 + 1) * 132 + ar0] = pb0.y;
        B[(aq0 + 2) * 132 + ar0] = pb0.z; B[(aq0 + 3) * 132 + ar0] = pb0.w;
        B[(aq1 + 0) * 132 + ar1] = pb1.x; B[(aq1 + 1) * 132 + ar1] = pb1.y;
        B[(aq1 + 2) * 132 + ar1] = pb1.z; B[(aq1 + 3) * 132 + ar1] = pb1.w;
    }
    __syncthreads();

#pragma unroll 1
    for (int kt = 0; kt < 64; ++kt) {
        const int cur = kt & 1;
        if (kt < 63) {
            const int k0 = (kt + 1) * 16;
            pa0 = *(const float4*)(aBase + (size_t)ar0 * DM + k0 + aq0);
            pa1 = *(const float4*)(aBase + (size_t)ar1 * DM + k0 + aq1);
            pb0 = *(const float4*)(bBase + (size_t)ar0 * IB + k0 + aq0);
            pb1 = *(const float4*)(bBase + (size_t)ar1 * IB + k0 + aq1);
        }
        const float* A = As[cur];
        const float* B = Bs[cur];
#pragma unroll
        for (int k = 0; k < 16; ++k) {
            float4 a0 = *(const float4*)(A + k * 132 + rb);
            float4 a1 = *(const float4*)(A + k * 132 + rb + 4);
            float4 b0 = *(const float4*)(B + k * 132 + nb1);
            float4 b1 = *(const float4*)(B + k * 132 + nb2);
            float av[8] = {a0.x, a0.y, a0.z, a0.w, a1.x, a1.y, a1.z, a1.w};
            float bv[8] = {b0.x, b0.y, b0.z, b0.w, b1.x, b1.y, b1.z, b1.w};
#pragma unroll
            for (int i = 0; i < 8; ++i)
#pragma unroll
                for (int j = 0; j < 8; ++j)
                    acc[i][j] = fmaf(av[i], bv[j], acc[i][j]);
        }
        if (kt < 63) {
            float* An = As[cur ^ 1]; float* Bn = Bs[cur ^ 1];
            An[(aq0 + 0) * 132 + ar0] = pa0.x; An[(aq0 + 1) * 132 + ar0] = pa0.y;
            An[(aq0 + 2) * 132 + ar0] = pa0.z; An[(aq0 + 3) * 132 + ar0] = pa0.w;
            An[(aq1 + 0) * 132 + ar1] = pa1.x; An[(aq1 + 1) * 132 + ar1] = pa1.y;
            An[(aq1 + 2) * 132 + ar1] = pa1.z; An[(aq1 + 3) * 132 + ar1] = pa1.w;
            Bn[(aq0 + 0) * 132 + ar0] = pb0.x; Bn[(aq0 + 1) * 132 + ar0] = pb0.y;
            Bn[(aq0 + 2) * 132 + ar0] = pb0.z; Bn[(aq0 + 3) * 132 + ar0] = pb0.w;
            Bn[(aq1 + 0) * 132 + ar1] = pb1.x; Bn[(aq1 + 1) * 132 + ar1] = pb1.y;
            Bn[(aq1 + 2) * 132 + ar1] = pb1.z; Bn[(aq1 + 3) * 132 + ar1] = pb1.w;
            __syncthreads();
        }
    }

    float* C = g_pre + (size_t)g * MROWS * DM + (size_t)blk * IB + (size_t)(ntile * 128);
#pragma unroll
    for (int i = 0; i < 8; ++i) {
        const size_t row = (size_t)(mtile * 128 + rb + i);
        *(float4*)(C + row * DM + nb1) = make_float4(acc[i][0], acc[i][1], acc[i][2], acc[i][3]);
        *(float4*)(C + row * DM + nb2) = make_float4(acc[i][4], acc[i][5], acc[i][6], acc[i][7]);
    }
}

// ---------------- kernel: single-term TF32 MMA GEMM (gates o,z) ------------
// (R8 version: [k][n] layout stride 136, tf32 convert at smem store,
//  register-prefetch double buffer, one sync per k-tile.)
__global__ __launch_bounds__(256, 2) void k_gemm_oz(const float* __restrict__ Wg) {
    __shared__ __align__(16) float As[2][16 * 136];
    __shared__ __align__(16) float Bs[2][16 * 136];

    const int mtile = blockIdx.x;
    const int ntile = blockIdx.y;
    const int g     = 2 + (blockIdx.z & 1);  // gate 2 or 3
    const int blk   = blockIdx.z >> 1;

    const int tid  = threadIdx.x;
    const int lane = tid & 31;
    const int wid  = tid >> 5;
    const int gid  = lane >> 2;
    const int tig  = lane & 3;
    const int warp_m = wid >> 2;             // 0..1
    const int warp_n = wid & 3;              // 0..3

    const float* aBase = g_xa + (size_t)(mtile * 128) * DM + blk * IB;
    const float* bBase = Wg + ((size_t)(g * 4 + blk)) * IB * IB + (size_t)(ntile * 128) * IB;

    const int s0 = tid, s1 = tid + 256;
    const int ar0 = s0 >> 2, aq0 = (s0 & 3) * 4;
    const int ar1 = s1 >> 2, aq1 = (s1 & 3) * 4;

    float4 acc[4][4];
#pragma unroll
    for (int mi = 0; mi < 4; ++mi)
#pragma unroll
        for (int ni = 0; ni < 4; ++ni) acc[mi][ni] = make_float4(0.f, 0.f, 0.f, 0.f);

    float4 pa0, pa1, pb0, pb1;
    pa0 = *(const float4*)(aBase + (size_t)ar0 * DM + aq0);
    pa1 = *(const float4*)(aBase + (size_t)ar1 * DM + aq1);
    pb0 = *(const float4*)(bBase + (size_t)ar0 * IB + aq0);
    pb1 = *(const float4*)(bBase + (size_t)ar1 * IB + aq1);
    {
        float* A = As[0]; float* B = Bs[0];
        A[(aq0 + 0) * 136 + ar0] = to_tf32(pa0.x); A[(aq0 + 1) * 136 + ar0] = to_tf32(pa0.y);
        A[(aq0 + 2) * 136 + ar0] = to_tf32(pa0.z); A[(aq0 + 3) * 136 + ar0] = to_tf32(pa0.w);
        A[(aq1 + 0) * 136 + ar1] = to_tf32(pa1.x); A[(aq1 + 1) * 136 + ar1] = to_tf32(pa1.y);
        A[(aq1 + 2) * 136 + ar1] = to_tf32(pa1.z); A[(aq1 + 3) * 136 + ar1] = to_tf32(pa1.w);
        B[(aq0 + 0) * 136 + ar0] = to_tf32(pb0.x); B[(aq0 + 1) * 136 + ar0] = to_tf32(pb0.y);
        B[(aq0 + 2) * 136 + ar0] = to_tf32(pb0.z); B[(aq0 + 3) * 136 + ar0] = to_tf32(pb0.w);
        B[(aq1 + 0) * 136 + ar1] = to_tf32(pb1.x); B[(aq1 + 1) * 136 + ar1] = to_tf32(pb1.y);
        B[(aq1 + 2) * 136 + ar1] = to_tf32(pb1.z); B[(aq1 + 3) * 136 + ar1] = to_tf32(pb1.w);
    }
    __syncthreads();

#pragma unroll 1
    for (int kt = 0; kt < 64; ++kt) {
        const int cur = kt & 1;
        if (kt < 63) {
            const int k0 = (kt + 1) * 16;
            pa0 = *(const float4*)(aBase + (size_t)ar0 * DM + k0 + aq0);
            pa1 = *(const float4*)(aBase + (size_t)ar1 * DM + k0 + aq1);
            pb0 = *(const float4*)(bBase + (size_t)ar0 * IB + k0 + aq0);
            pb1 = *(const float4*)(bBase + (size_t)ar1 * IB + k0 + aq1);
        }
        const float* A = As[cur];
        const float* B = Bs[cur];
#pragma unroll
        for (int ks = 0; ks < 16; ks += 8) {
            float a_[4][4];
#pragma unroll
            for (int mi = 0; mi < 4; ++mi) {
                const int rm = warp_m * 64 + mi * 16 + gid;
                a_[mi][0] = A[(ks + tig) * 136 + rm];
                a_[mi][1] = A[(ks + tig) * 136 + rm + 8];
                a_[mi][2] = A[(ks + tig + 4) * 136 + rm];
                a_[mi][3] = A[(ks + tig + 4) * 136 + rm + 8];
            }
#pragma unroll
            for (int ni = 0; ni < 4; ++ni) {
                const int nb = warp_n * 32 + ni * 8 + gid;
                const float b0 = B[(ks + tig) * 136 + nb];
                const float b1 = B[(ks + tig + 4) * 136 + nb];
#pragma unroll
                for (int mi = 0; mi < 4; ++mi)
                    mma_tf32(acc[mi][ni], a_[mi], b0, b1);
            }
        }
        if (kt < 63) {
            float* An = As[cur ^ 1]; float* Bn = Bs[cur ^ 1];
            An[(aq0 + 0) * 136 + ar0] = to_tf32(pa0.x); An[(aq0 + 1) * 136 + ar0] = to_tf32(pa0.y);
            An[(aq0 + 2) * 136 + ar0] = to_tf32(pa0.z); An[(aq0 + 3) * 136 + ar0] = to_tf32(pa0.w);
            An[(aq1 + 0) * 136 + ar1] = to_tf32(pa1.x); An[(aq1 + 1) * 136 + ar1] = to_tf32(pa1.y);
            An[(aq1 + 2) * 136 + ar1] = to_tf32(pa1.z); An[(aq1 + 3) * 136 + ar1] = to_tf32(pa1.w);
            Bn[(aq0 + 0) * 136 + ar0] = to_tf32(pb0.x); Bn[(aq0 + 1) * 136 + ar0] = to_tf32(pb0.y);
            Bn[(aq0 + 2) * 136 + ar0] = to_tf32(pb0.z); Bn[(aq0 + 3) * 136 + ar0] = to_tf32(pb0.w);
            Bn[(aq1 + 0) * 136 + ar1] = to_tf32(pb1.x); Bn[(aq1 + 1) * 136 + ar1] = to_tf32(pb1.y);
            Bn[(aq1 + 2) * 136 + ar1] = to_tf32(pb1.z); Bn[(aq1 + 3) * 136 + ar1] = to_tf32(pb1.w);
            __syncthreads();
        }
    }

    float* C = g_pre + (size_t)g * MROWS * DM + (size_t)blk * IB;
#pragma unroll
    for (int mi = 0; mi < 4; ++mi) {
#pragma unroll
        for (int ni = 0; ni < 4; ++ni) {
            const int row = mtile * 128 + warp_m * 64 + mi * 16 + gid;
            const int col = ntile * 128 + warp_n * 32 + ni * 8 + tig * 2;
            *(float2*)(C + (size_t)row * DM + col) = make_float2(acc[mi][ni].x, acc[mi][ni].y);
            *(float2*)(C + (size_t)(row + 8) * DM + col) = make_float2(acc[mi][ni].z, acc[mi][ni].w);
        }
    }
}

// ---------------- kernel: row-wise gates (stats fp64, values fp32) ----------
__global__ __launch_bounds__(512) void k_pass2(const float* __restrict__ b_gates,
                                               const float* __restrict__ lng,
                                               const float* __restrict__ lnb) {
    __shared__ double s_red[16 * 8];
    const int tid = threadIdx.x;
    const int d0 = tid * 8;

    for (int row = blockIdx.x; row < MROWS; row += gridDim.x) {
        float p[4][8];
#pragma unroll
        for (int gg = 0; gg < 4; ++gg) {
            const float* base = g_pre + ((size_t)gg * MROWS + row) * DM + d0;
            float4 u = *(const float4*)(base);
            float4 v = *(const float4*)(base + 4);
            const float* bg = b_gates + gg * DM + d0;
            float4 w = *(const float4*)(bg);
            float4 y = *(const float4*)(bg + 4);
            p[gg][0] = __fadd_rn(u.x, w.x); p[gg][1] = __fadd_rn(u.y, w.y);
            p[gg][2] = __fadd_rn(u.z, w.z); p[gg][3] = __fadd_rn(u.w, w.w);
            p[gg][4] = __fadd_rn(v.x, y.x); p[gg][5] = __fadd_rn(v.y, y.y);
            p[gg][6] = __fadd_rn(v.z, y.z); p[gg][7] = __fadd_rn(v.w, y.w);
        }
        double v8[8];
#pragma unroll
        for (int gg = 0; gg < 4; ++gg) {
            double s = 0.0, q = 0.0;
#pragma unroll
            for (int c = 0; c < 8; ++c) {
                double pv = (double)p[gg][c];
                s += pv; q += pv * pv;
            }
            v8[2 * gg] = s; v8[2 * gg + 1] = q;
        }
        block_reduce_d<8>(v8, s_red);
        double mu[4], rs[4];
#pragma unroll
        for (int gg = 0; gg < 4; ++gg) {
            mu[gg] = v8[2 * gg] * (1.0 / DM);
            double var = v8[2 * gg + 1] * (1.0 / DM) - mu[gg] * mu[gg];
            rs[gg] = 1.0 / sqrt(var + EPSD);
        }
        float iv[8], cv[8], ov[8];
#pragma unroll
        for (int c = 0; c < 8; ++c) {
            const int d = d0 + c;
            float li = (float)((((double)p[0][c] - mu[0]) * rs[0]) * (double)lng[d]          + (double)lnb[d]);
            float lf = (float)((((double)p[1][c] - mu[1]) * rs[1]) * (double)lng[DM + d]     + (double)lnb[DM + d]);
            float lo = (float)((((double)p[2][c] - mu[2]) * rs[2]) * (double)lng[2 * DM + d] + (double)lnb[2 * DM + d]);
            float lz = (float)((((double)p[3][c] - mu[3]) * rs[3]) * (double)lng[3 * DM + d] + (double)lnb[3 * DM + d]);
            float m  = fmaxf(li, lf);
            float q  = __fadd_rn(li, -m);
            float ii = (float)exp((double)q);        // near-correctly-rounded f32 exp
            float zz = tanh_xla(lz);
            ov[c] = logistic_xla(lo);
            iv[c] = ii;
            cv[c] = __fmul_rn(ii, zz);
        }
        {
            float* ob = g_obuf + (size_t)row * DM + d0;
            *(float4*)(ob)     = make_float4(ov[0], ov[1], ov[2], ov[3]);
            *(float4*)(ob + 4) = make_float4(ov[4], ov[5], ov[6], ov[7]);
        }
        double v4[4] = {0.0, 0.0, 0.0, 0.0};
#pragma unroll
        for (int c = 0; c < 8; ++c) {
            double cd = (double)cv[c], id = (double)iv[c];
            v4[0] += cd; v4[1] += cd * cd;
            v4[2] += id; v4[3] += id * id;
        }
        block_reduce_d<4>(v4, s_red);
        const double muc = v4[0] * (1.0 / DM);
        const double rsc = 1.0 / sqrt(v4[1] * (1.0 / DM) - muc * muc + EPSD);
        const double mui = v4[2] * (1.0 / DM);
        const double rsi = 1.0 / sqrt(v4[3] * (1.0 / DM) - mui * mui + EPSD);
        float lc[8], ln_[8];
#pragma unroll
        for (int c = 0; c < 8; ++c) {
            const int d = d0 + c;
            lc[c]  = (float)((((double)cv[c] - muc) * rsc) * (double)lng[4 * DM + d] + (double)lnb[4 * DM + d]);
            ln_[c] = (float)((((double)iv[c] - mui) * rsi) * (double)lng[5 * DM + d] + (double)lnb[5 * DM + d]);
        }
        float* pc = g_lnct + (size_t)row * DM + d0;
        float* pn = g_lni + (size_t)row * DM + d0;
        *(float4*)(pc)     = make_float4(lc[0], lc[1], lc[2], lc[3]);
        *(float4*)(pc + 4) = make_float4(lc[4], lc[5], lc[6], lc[7]);
        *(float4*)(pn)     = make_float4(ln_[0], ln_[1], ln_[2], ln_[3]);
        *(float4*)(pn + 4) = make_float4(ln_[4], ln_[5], ln_[6], ln_[7]);
    }
}

// ---------------- kernel: SEQUENTIAL ascending-row fp32 column sums ---------
__global__ __launch_bounds__(32) void k_redsum() {
    const int d = blockIdx.x * 32 + threadIdx.x;
    const float* pc = g_lnct + d;
    const float* pn = g_lni + d;
    float ac = 0.0f, an = 0.0f;
#pragma unroll 16
    for (int row = 0; row < MROWS; ++row) {
        ac = __fadd_rn(ac, __ldg(pc + (size_t)row * DM));
        an = __fadd_rn(an, __ldg(pn + (size_t)row * DM));
    }
    const float cm = __fmul_rn(ac, 1.0f / MROWS);
    const float nm = __fmul_rn(an, 1.0f / MROWS);
    g_ratio[d] = __fdiv_rn(cm, nm);
}

// ---------------- kernel: ht pass (non-amplified; fp64 stats) ----------------
__global__ __launch_bounds__(512) void k_pass3(const float* __restrict__ lng,
                                               const float* __restrict__ lnb) {
    __shared__ double s_htm[DM];
    __shared__ double s_red[16 * 2];
    const int tid = threadIdx.x;
    for (int d = tid; d < DM; d += 512) s_htm[d] = 0.0;
    __syncthreads();
    const int d0 = tid * 8;
    float rr[8];
#pragma unroll
    for (int c = 0; c < 8; ++c) rr[c] = g_ratio[d0 + c];

    for (int row = blockIdx.x; row < MROWS; row += gridDim.x) {
        const float* ob = g_obuf + (size_t)row * DM + d0;
        float4 u = *(const float4*)(ob);
        float4 v = *(const float4*)(ob + 4);
        float h[8] = {__fmul_rn(u.x, rr[0]), __fmul_rn(u.y, rr[1]),
                      __fmul_rn(u.z, rr[2]), __fmul_rn(u.w, rr[3]),
                      __fmul_rn(v.x, rr[4]), __fmul_rn(v.y, rr[5]),
                      __fmul_rn(v.z, rr[6]), __fmul_rn(v.w, rr[7])};
        double v2[2] = {0.0, 0.0};
#pragma unroll
        for (int c = 0; c < 8; ++c) { double hd = (double)h[c]; v2[0] += hd; v2[1] += hd * hd; }
        block_reduce_d<2>(v2, s_red);
        const double mu = v2[0] * (1.0 / DM);
        const double rs = 1.0 / sqrt(v2[1] * (1.0 / DM) - mu * mu + EPSD);
#pragma unroll
        for (int c = 0; c < 8; ++c) {
            const int d = d0 + c;
            s_htm[d] += ((double)h[c] - mu) * rs * (double)lng[6 * DM + d] + (double)lnb[6 * DM + d];
        }
    }
    __syncthreads();
    for (int d = tid; d < DM; d += 512) atomicAdd(&g_htmsum[d], s_htm[d]);
}

// ---------------- kernel: slstm_out = LN(mean ht) (fp64) ----------------
__global__ __launch_bounds__(512) void k_pass4(const float* __restrict__ lng,
                                               const float* __restrict__ lnb) {
    __shared__ double s_red[16 * 2];
    const int tid = threadIdx.x;
    const int d0 = tid * 8;
    double h[8];
#pragma unroll
    for (int c = 0; c < 8; ++c) h[c] = g_htmsum[d0 + c] * (1.0 / MROWS);
    double v2[2] = {0.0, 0.0};
#pragma unroll
    for (int c = 0; c < 8; ++c) { v2[0] += h[c]; v2[1] += h[c] * h[c]; }
    block_reduce_d<2>(v2, s_red);
    const double mu = v2[0] * (1.0 / DM);
    const double rs = 1.0 / sqrt(v2[1] * (1.0 / DM) - mu * mu + EPSD);
#pragma unroll
    for (int c = 0; c < 8; ++c) {
        const int d = d0 + c;
        g_s[d] = (h[c] - mu) * rs * (double)lng[7 * DM + d] + (double)lnb[7 * DM + d];
    }
}

// ---------------- kernel: left/right GEMVs + gelu + product (fp64) ----------
__global__ __launch_bounds__(128) void k_pass5(const float* __restrict__ Wl,
                                               const float* __restrict__ bl,
                                               const float* __restrict__ Wr,
                                               const float* __restrict__ br) {
    __shared__ double s_red[4 * 2];
    const int j = blockIdx.x;
    const int tid = threadIdx.x;
    double v2[2] = {0.0, 0.0};
    const float* wl = Wl + (size_t)j * DM;
    const float* wr = Wr + (size_t)j * DM;
    for (int d = tid; d < DM; d += 128) {
        const double s = g_s[d];
        v2[0] += s * (double)wl[d];
        v2[1] += s * (double)wr[d];
    }
    block_reduce_d<2>(v2, s_red);
    if (tid == 0) {
        const double left = v2[0] + (double)bl[j];
        double right = v2[1] + (double)br[j];
        right = 0.5 * right * (1.0 + erf(right * 0.7071067811865475244));  // exact gelu
        g_v[j] = left * right;
    }
}

// ---------------- kernel: LN over DFF (fp64) ----------------
__global__ __launch_bounds__(512) void k_pass6a(const float* __restrict__ og,
                                                const float* __restrict__ ob) {
    __shared__ double s_red[16 * 2];
    const int tid = threadIdx.x;
    double v2[2] = {0.0, 0.0};
    for (int jj = tid; jj < DFF; jj += 512) {
        const double x = g_v[jj];
        v2[0] += x; v2[1] += x * x;
    }
    block_reduce_d<2>(v2, s_red);
    const double mu = v2[0] * (1.0 / DFF);
    const double rs = 1.0 / sqrt(v2[1] * (1.0 / DFF) - mu * mu + EPSD);
    for (int jj = tid; jj < DFF; jj += 512)
        g_u[jj] = (g_v[jj] - mu) * rs * (double)og[jj] + (double)ob[jj];
}

// ---------------- kernel: final projection GEMV (fp64) ----------------
__global__ __launch_bounds__(128) void k_pass6b(const float* __restrict__ Wp,
                                                const float* __restrict__ bp,
                                                float* __restrict__ out) {
    __shared__ double s_red[4 * 1];
    const int d = blockIdx.x;
    const int tid = threadIdx.x;
    double acc[1] = {0.0};
    const float* wp = Wp + (size_t)d * DFF;
    for (int jj = tid; jj < DFF; jj += 128) acc[0] += g_u[jj] * (double)wp[jj];
    block_reduce_d<1>(acc, s_red);
    if (tid == 0) out[d] = (float)(acc[0] + (double)bp[d]);
}

// ---------------- launcher ----------------
extern "C" void kernel_launch(void* const* d_in, const int* in_sizes, int n_in,
                              void* d_out, int out_size) {
    const float* x      = (const float*)d_in[0];
    const float* Wg     = (const float*)d_in[1];
    const float* bgates = (const float*)d_in[2];
    // d_in[3] = Wr_gates: multiplies zero initial state -> unused
    const float* lng    = (const float*)d_in[4];
    const float* lnb    = (const float*)d_in[5];
    const float* lnoutg = (const float*)d_in[6];
    const float* lnoutb = (const float*)d_in[7];
    const float* Wl     = (const float*)d_in[8];
    const float* bl     = (const float*)d_in[9];
    const float* Wr     = (const float*)d_in[10];
    const float* br     = (const float*)d_in[11];
    const float* Wp     = (const float*)d_in[12];
    const float* bp     = (const float*)d_in[13];
    float* out = (float*)d_out;

    // Secondary stream + events for a parallel branch in the captured graph.
    // Created once (driver objects, not device memory); graph replay contains
    // only the captured device work, which is identical on every capture.
    static cudaStream_t s_oz = 0;
    static cudaEvent_t  e_fork = 0, e_join = 0;
    if (s_oz == 0) {
        cudaStreamCreateWithFlags(&s_oz, cudaStreamNonBlocking);
        cudaEventCreateWithFlags(&e_fork, cudaEventDisableTiming);
        cudaEventCreateWithFlags(&e_join, cudaEventDisableTiming);
    }

    k_zero<<<8, 512>>>();
    k_silu<<<(MROWS * (size_t)DM) / (256 * 4), 256>>>(x);

    // Fork: oz-GEMM (latency-bound) runs concurrently with if-GEMM (fma-bound).
    cudaEventRecord(e_fork, 0);
    cudaStreamWaitEvent(s_oz, e_fork, 0);
    k_gemm_oz<<<dim3(64, 8, 8), 256, 0, s_oz>>>(Wg);
    k_gemm_if<<<dim3(64, 8, 8), 256>>>(Wg);
    cudaEventRecord(e_join, s_oz);
    cudaStreamWaitEvent(0, e_join, 0);

    k_pass2<<<296, 512>>>(bgates, lng, lnb);
    k_redsum<<<DM / 32, 32>>>();
    k_pass3<<<296, 512>>>(lng, lnb);
    k_pass4<<<1, 512>>>(lng, lnb);
    k_pass5<<<DFF, 128>>>(Wl, bl, Wr, br);
    k_pass6a<<<1, 512>>>(lnoutg, lnoutb);
    k_pass6b<<<DM, 128>>>(Wp, bp, out);
}

// round 14
// speedup vs baseline: 1.6007x; 1.6007x over previous
#include <cuda_runtime.h>
#include <math.h>
#include <stdint.h>

// ---------------- problem constants ----------------
#define DM      4096
#define MROWS   8192          // B*N = 4*2048
#define IB      1024          // block size (DM / 4 blocks)
#define DFF     5461
#define EPSD    1e-5

// ---------------- scratch (device globals; no allocations allowed) ----------
__device__ float  g_xa[(size_t)MROWS * DM];        // 128 MB silu(x)
__device__ float  g_pre[4ULL * MROWS * DM];        // 512 MB gate pre-activations
__device__ float  g_lnct[(size_t)MROWS * DM];      // 128 MB LN(i*z) values
__device__ float  g_lni[(size_t)MROWS * DM];       // 128 MB LN(i) values
__device__ float  g_obuf[(size_t)MROWS * DM];      // 128 MB o-gate values
__device__ float  g_ratio[DM];                     // ct/nt (fp32, ref-matched)
__device__ double g_htmsum[DM];
__device__ double g_s[DM];                         // slstm_out
__device__ double g_v[DFF];                        // left*right (pre-LN)
__device__ double g_u[DFF];                        // LN'd

// ---------------- XLA-matched elementwise math ----------------
__device__ __forceinline__ float tanh_xla(float x) {
    const float kMax = 7.90531110763549805f;
    float cx = fminf(fmaxf(x, -kMax), kMax);
    float x2 = __fmul_rn(cx, cx);
    float p = fmaf(x2, -2.76076847742355e-16f, 2.00018790482477e-13f);
    p = fmaf(p, x2, -8.60467152213735e-11f);
    p = fmaf(p, x2, 5.12229709037114e-08f);
    p = fmaf(p, x2, 1.48572235717979e-05f);
    p = fmaf(p, x2, 6.37261928875436e-04f);
    p = fmaf(p, x2, 4.89352455891786e-03f);
    p = __fmul_rn(cx, p);
    float q = fmaf(x2, 1.19825839466702e-06f, 1.18534705686654e-04f);
    q = fmaf(q, x2, 2.26843463243900e-03f);
    q = fmaf(q, x2, 4.89352518554385e-03f);
    float r = __fdiv_rn(p, q);
    return (fabsf(x) < 0.0004f) ? x : r;
}

__device__ __forceinline__ float logistic_xla(float x) {
    return fmaf(0.5f, tanh_xla(__fmul_rn(0.5f, x)), 0.5f);
}

__device__ __forceinline__ float silu_xla(float x) {
    return __fmul_rn(x, logistic_xla(x));
}

// ---------------- TF32 helpers ----------------
__device__ __forceinline__ float to_tf32(float v) {
    unsigned u;
    asm("cvt.rna.tf32.f32 %0, %1;" : "=r"(u) : "f"(v));
    return __uint_as_float(u);
}

__device__ __forceinline__ void mma_tf32(float4& d, const float* a, float b0, float b1) {
    asm volatile(
        "mma.sync.aligned.m16n8k8.row.col.f32.tf32.tf32.f32 "
        "{%0,%1,%2,%3}, {%4,%5,%6,%7}, {%8,%9}, {%0,%1,%2,%3};\n"
        : "+f"(d.x), "+f"(d.y), "+f"(d.z), "+f"(d.w)
        : "r"(__float_as_uint(a[0])), "r"(__float_as_uint(a[1])),
          "r"(__float_as_uint(a[2])), "r"(__float_as_uint(a[3])),
          "r"(__float_as_uint(b0)), "r"(__float_as_uint(b1)));
}

// ---------------- fp64 block reduce ----------------
template <int NV>
__device__ __forceinline__ void block_reduce_d(double* v, double* sred) {
    const int lane = threadIdx.x & 31;
    const int wid  = threadIdx.x >> 5;
    const int nw   = (blockDim.x + 31) >> 5;
#pragma unroll
    for (int i = 0; i < NV; ++i) {
        double x = v[i];
#pragma unroll
        for (int o = 16; o > 0; o >>= 1) x += __shfl_xor_sync(0xffffffffu, x, o);
        v[i] = x;
    }
    __syncthreads();
    if (lane == 0) {
#pragma unroll
        for (int i = 0; i < NV; ++i) sred[wid * NV + i] = v[i];
    }
    __syncthreads();
    if (wid == 0) {
#pragma unroll
        for (int i = 0; i < NV; ++i) {
            double x = (lane < nw) ? sred[lane * NV + i] : 0.0;
#pragma unroll
            for (int o = 16; o > 0; o >>= 1) x += __shfl_xor_sync(0xffffffffu, x, o);
            if (lane == 0) sred[i] = x;
        }
    }
    __syncthreads();
#pragma unroll
    for (int i = 0; i < NV; ++i) v[i] = sred[i];
    __syncthreads();
}

// ---------------- kernel: zero + silu ----------------
__global__ void k_zero() {
    int idx = blockIdx.x * blockDim.x + threadIdx.x;
    if (idx < DM) g_htmsum[idx] = 0.0;
}

__global__ __launch_bounds__(256) void k_silu(const float* __restrict__ x) {
    size_t i = ((size_t)blockIdx.x * 256 + threadIdx.x) * 4;
    float4 v = *(const float4*)(x + i);
    v.x = silu_xla(v.x); v.y = silu_xla(v.y); v.z = silu_xla(v.z); v.w = silu_xla(v.w);
    *(float4*)(g_xa + i) = v;
}

// ---------------- kernel: scalar fp32 SGEMM (gates i,f), ascending-k -------
// Bit-exact match of XLA's sgemm chains (amplified denominator path).
__global__ __launch_bounds__(256, 2) void k_gemm_if(const float* __restrict__ Wg) {
    __shared__ __align__(16) float As[2][16 * 132];
    __shared__ __align__(16) float Bs[2][16 * 132];

    const int mtile = blockIdx.x;
    const int ntile = blockIdx.y;
    const int g     = blockIdx.z & 1;        // gate 0 or 1
    const int blk   = blockIdx.z >> 1;

    const int tid = threadIdx.x;
    const int tx  = tid & 15;
    const int ty  = tid >> 4;
    const int rb  = ty * 8;
    const int nb1 = tx * 4;
    const int nb2 = 64 + tx * 4;

    const float* aBase = g_xa + (size_t)(mtile * 128) * DM + blk * IB;
    const float* bBase = Wg + ((size_t)(g * 4 + blk)) * IB * IB + (size_t)(ntile * 128) * IB;

    const int s0 = tid, s1 = tid + 256;
    const int ar0 = s0 >> 2, aq0 = (s0 & 3) * 4;
    const int ar1 = s1 >> 2, aq1 = (s1 & 3) * 4;

    float acc[8][8];
#pragma unroll
    for (int i = 0; i < 8; ++i)
#pragma unroll
        for (int j = 0; j < 8; ++j) acc[i][j] = 0.0f;

    float4 pa0, pa1, pb0, pb1;
    pa0 = *(const float4*)(aBase + (size_t)ar0 * DM + aq0);
    pa1 = *(const float4*)(aBase + (size_t)ar1 * DM + aq1);
    pb0 = *(const float4*)(bBase + (size_t)ar0 * IB + aq0);
    pb1 = *(const float4*)(bBase + (size_t)ar1 * IB + aq1);
    {
        float* A = As[0]; float* B = Bs[0];
        A[(aq0 + 0) * 132 + ar0] = pa0.x; A[(aq0 + 1) * 132 + ar0] = pa0.y;
        A[(aq0 + 2) * 132 + ar0] = pa0.z; A[(aq0 + 3) * 132 + ar0] = pa0.w;
        A[(aq1 + 0) * 132 + ar1] = pa1.x; A[(aq1 + 1) * 132 + ar1] = pa1.y;
        A[(aq1 + 2) * 132 + ar1] = pa1.z; A[(aq1 + 3) * 132 + ar1] = pa1.w;
        B[(aq0 + 0) * 132 + ar0] = pb0.x; B[(aq0 + 1) * 132 + ar0] = pb0.y;
        B[(aq0 + 2) * 132 + ar0] = pb0.z; B[(aq0 + 3) * 132 + ar0] = pb0.w;
        B[(aq1 + 0) * 132 + ar1] = pb1.x; B[(aq1 + 1) * 132 + ar1] = pb1.y;
        B[(aq1 + 2) * 132 + ar1] = pb1.z; B[(aq1 + 3) * 132 + ar1] = pb1.w;
    }
    __syncthreads();

#pragma unroll 1
    for (int kt = 0; kt < 64; ++kt) {
        const int cur = kt & 1;
        if (kt < 63) {
            const int k0 = (kt + 1) * 16;
            pa0 = *(const float4*)(aBase + (size_t)ar0 * DM + k0 + aq0);
            pa1 = *(const float4*)(aBase + (size_t)ar1 * DM + k0 + aq1);
            pb0 = *(const float4*)(bBase + (size_t)ar0 * IB + k0 + aq0);
            pb1 = *(const float4*)(bBase + (size_t)ar1 * IB + k0 + aq1);
        }
        const float* A = As[cur];
        const float* B = Bs[cur];
#pragma unroll
        for (int k = 0; k < 16; ++k) {
            float4 a0 = *(const float4*)(A + k * 132 + rb);
            float4 a1 = *(const float4*)(A + k * 132 + rb + 4);
            float4 b0 = *(const float4*)(B + k * 132 + nb1);
            float4 b1 = *(const float4*)(B + k * 132 + nb2);
            float av[8] = {a0.x, a0.y, a0.z, a0.w, a1.x, a1.y, a1.z, a1.w};
            float bv[8] = {b0.x, b0.y, b0.z, b0.w, b1.x, b1.y, b1.z, b1.w};
#pragma unroll
            for (int i = 0; i < 8; ++i)
#pragma unroll
                for (int j = 0; j < 8; ++j)
                    acc[i][j] = fmaf(av[i], bv[j], acc[i][j]);
        }
        if (kt < 63) {
            float* An = As[cur ^ 1]; float* Bn = Bs[cur ^ 1];
            An[(aq0 + 0) * 132 + ar0] = pa0.x; An[(aq0 + 1) * 132 + ar0] = pa0.y;
            An[(aq0 + 2) * 132 + ar0] = pa0.z; An[(aq0 + 3) * 132 + ar0] = pa0.w;
            An[(aq1 + 0) * 132 + ar1] = pa1.x; An[(aq1 + 1) * 132 + ar1] = pa1.y;
            An[(aq1 + 2) * 132 + ar1] = pa1.z; An[(aq1 + 3) * 132 + ar1] = pa1.w;
            Bn[(aq0 + 0) * 132 + ar0] = pb0.x; Bn[(aq0 + 1) * 132 + ar0] = pb0.y;
            Bn[(aq0 + 2) * 132 + ar0] = pb0.z; Bn[(aq0 + 3) * 132 + ar0] = pb0.w;
            Bn[(aq1 + 0) * 132 + ar1] = pb1.x; Bn[(aq1 + 1) * 132 + ar1] = pb1.y;
            Bn[(aq1 + 2) * 132 + ar1] = pb1.z; Bn[(aq1 + 3) * 132 + ar1] = pb1.w;
            __syncthreads();
        }
    }

    float* C = g_pre + (size_t)g * MROWS * DM + (size_t)blk * IB + (size_t)(ntile * 128);
#pragma unroll
    for (int i = 0; i < 8; ++i) {
        const size_t row = (size_t)(mtile * 128 + rb + i);
        *(float4*)(C + row * DM + nb1) = make_float4(acc[i][0], acc[i][1], acc[i][2], acc[i][3]);
        *(float4*)(C + row * DM + nb2) = make_float4(acc[i][4], acc[i][5], acc[i][6], acc[i][7]);
    }
}

// ---------------- kernel: single-term TF32 MMA GEMM (gates o,z) ------------
// 512 threads / 16 warps per 128x128 tile -> 32 warps/SM (2 CTAs), doubling
// occupancy vs the 256-thread version to hide LDS/HMMA latency.
// Each warp: 32x32 sub-tile = 2 m16 frags x 4 n8 frags (32 acc regs).
// Same [k][n] stride-136 layout, tf32 at smem store, double buffered.
__global__ __launch_bounds__(512, 2) void k_gemm_oz(const float* __restrict__ Wg) {
    __shared__ __align__(16) float As[2][16 * 136];
    __shared__ __align__(16) float Bs[2][16 * 136];

    const int mtile = blockIdx.x;
    const int ntile = blockIdx.y;
    const int g     = 2 + (blockIdx.z & 1);  // gate 2 or 3
    const int blk   = blockIdx.z >> 1;

    const int tid  = threadIdx.x;
    const int lane = tid & 31;
    const int wid  = tid >> 5;               // 0..15
    const int gid  = lane >> 2;
    const int tig  = lane & 3;
    const int warp_m = wid >> 2;             // 0..3
    const int warp_n = wid & 3;              // 0..3

    const float* aBase = g_xa + (size_t)(mtile * 128) * DM + blk * IB;
    const float* bBase = Wg + ((size_t)(g * 4 + blk)) * IB * IB + (size_t)(ntile * 128) * IB;

    const int ar = tid >> 2;                 // 0..127
    const int aq = (tid & 3) * 4;            // 0,4,8,12

    float4 acc[2][4];
#pragma unroll
    for (int mi = 0; mi < 2; ++mi)
#pragma unroll
        for (int ni = 0; ni < 4; ++ni) acc[mi][ni] = make_float4(0.f, 0.f, 0.f, 0.f);

    float4 pa, pb;
    pa = *(const float4*)(aBase + (size_t)ar * DM + aq);
    pb = *(const float4*)(bBase + (size_t)ar * IB + aq);
    {
        float* A = As[0]; float* B = Bs[0];
        A[(aq + 0) * 136 + ar] = to_tf32(pa.x); A[(aq + 1) * 136 + ar] = to_tf32(pa.y);
        A[(aq + 2) * 136 + ar] = to_tf32(pa.z); A[(aq + 3) * 136 + ar] = to_tf32(pa.w);
        B[(aq + 0) * 136 + ar] = to_tf32(pb.x); B[(aq + 1) * 136 + ar] = to_tf32(pb.y);
        B[(aq + 2) * 136 + ar] = to_tf32(pb.z); B[(aq + 3) * 136 + ar] = to_tf32(pb.w);
    }
    __syncthreads();

#pragma unroll 1
    for (int kt = 0; kt < 64; ++kt) {
        const int cur = kt & 1;
        if (kt < 63) {
            const int k0 = (kt + 1) * 16;
            pa = *(const float4*)(aBase + (size_t)ar * DM + k0 + aq);
            pb = *(const float4*)(bBase + (size_t)ar * IB + k0 + aq);
        }
        const float* A = As[cur];
        const float* B = Bs[cur];
#pragma unroll
        for (int ks = 0; ks < 16; ks += 8) {
            float a_[2][4];
#pragma unroll
            for (int mi = 0; mi < 2; ++mi) {
                const int rm = warp_m * 32 + mi * 16 + gid;
                a_[mi][0] = A[(ks + tig) * 136 + rm];
                a_[mi][1] = A[(ks + tig) * 136 + rm + 8];
                a_[mi][2] = A[(ks + tig + 4) * 136 + rm];
                a_[mi][3] = A[(ks + tig + 4) * 136 + rm + 8];
            }
#pragma unroll
            for (int ni = 0; ni < 4; ++ni) {
                const int nb = warp_n * 32 + ni * 8 + gid;
                const float b0 = B[(ks + tig) * 136 + nb];
                const float b1 = B[(ks + tig + 4) * 136 + nb];
#pragma unroll
                for (int mi = 0; mi < 2; ++mi)
                    mma_tf32(acc[mi][ni], a_[mi], b0, b1);
            }
        }
        if (kt < 63) {
            float* An = As[cur ^ 1]; float* Bn = Bs[cur ^ 1];
            An[(aq + 0) * 136 + ar] = to_tf32(pa.x); An[(aq + 1) * 136 + ar] = to_tf32(pa.y);
            An[(aq + 2) * 136 + ar] = to_tf32(pa.z); An[(aq + 3) * 136 + ar] = to_tf32(pa.w);
            Bn[(aq + 0) * 136 + ar] = to_tf32(pb.x); Bn[(aq + 1) * 136 + ar] = to_tf32(pb.y);
            Bn[(aq + 2) * 136 + ar] = to_tf32(pb.z); Bn[(aq + 3) * 136 + ar] = to_tf32(pb.w);
            __syncthreads();
        }
    }

    float* C = g_pre + (size_t)g * MROWS * DM + (size_t)blk * IB;
#pragma unroll
    for (int mi = 0; mi < 2; ++mi) {
#pragma unroll
        for (int ni = 0; ni < 4; ++ni) {
            const int row = mtile * 128 + warp_m * 32 + mi * 16 + gid;
            const int col = ntile * 128 + warp_n * 32 + ni * 8 + tig * 2;
            *(float2*)(C + (size_t)row * DM + col) = make_float2(acc[mi][ni].x, acc[mi][ni].y);
            *(float2*)(C + (size_t)(row + 8) * DM + col) = make_float2(acc[mi][ni].z, acc[mi][ni].w);
        }
    }
}

// ---------------- kernel: row-wise gates (stats fp64, values fp32) ----------
__global__ __launch_bounds__(512) void k_pass2(const float* __restrict__ b_gates,
                                               const float* __restrict__ lng,
                                               const float* __restrict__ lnb) {
    __shared__ double s_red[16 * 8];
    const int tid = threadIdx.x;
    const int d0 = tid * 8;

    for (int row = blockIdx.x; row < MROWS; row += gridDim.x) {
        float p[4][8];
#pragma unroll
        for (int gg = 0; gg < 4; ++gg) {
            const float* base = g_pre + ((size_t)gg * MROWS + row) * DM + d0;
            float4 u = *(const float4*)(base);
            float4 v = *(const float4*)(base + 4);
            const float* bg = b_gates + gg * DM + d0;
            float4 w = *(const float4*)(bg);
            float4 y = *(const float4*)(bg + 4);
            p[gg][0] = __fadd_rn(u.x, w.x); p[gg][1] = __fadd_rn(u.y, w.y);
            p[gg][2] = __fadd_rn(u.z, w.z); p[gg][3] = __fadd_rn(u.w, w.w);
            p[gg][4] = __fadd_rn(v.x, y.x); p[gg][5] = __fadd_rn(v.y, y.y);
            p[gg][6] = __fadd_rn(v.z, y.z); p[gg][7] = __fadd_rn(v.w, y.w);
        }
        double v8[8];
#pragma unroll
        for (int gg = 0; gg < 4; ++gg) {
            double s = 0.0, q = 0.0;
#pragma unroll
            for (int c = 0; c < 8; ++c) {
                double pv = (double)p[gg][c];
                s += pv; q += pv * pv;
            }
            v8[2 * gg] = s; v8[2 * gg + 1] = q;
        }
        block_reduce_d<8>(v8, s_red);
        double mu[4], rs[4];
#pragma unroll
        for (int gg = 0; gg < 4; ++gg) {
            mu[gg] = v8[2 * gg] * (1.0 / DM);
            double var = v8[2 * gg + 1] * (1.0 / DM) - mu[gg] * mu[gg];
            rs[gg] = 1.0 / sqrt(var + EPSD);
        }
        float iv[8], cv[8], ov[8];
#pragma unroll
        for (int c = 0; c < 8; ++c) {
            const int d = d0 + c;
            float li = (float)((((double)p[0][c] - mu[0]) * rs[0]) * (double)lng[d]          + (double)lnb[d]);
            float lf = (float)((((double)p[1][c] - mu[1]) * rs[1]) * (double)lng[DM + d]     + (double)lnb[DM + d]);
            float lo = (float)((((double)p[2][c] - mu[2]) * rs[2]) * (double)lng[2 * DM + d] + (double)lnb[2 * DM + d]);
            float lz = (float)((((double)p[3][c] - mu[3]) * rs[3]) * (double)lng[3 * DM + d] + (double)lnb[3 * DM + d]);
            float m  = fmaxf(li, lf);
            float q  = __fadd_rn(li, -m);
            float ii = (float)exp((double)q);        // near-correctly-rounded f32 exp
            float zz = tanh_xla(lz);
            ov[c] = logistic_xla(lo);
            iv[c] = ii;
            cv[c] = __fmul_rn(ii, zz);
        }
        {
            float* ob = g_obuf + (size_t)row * DM + d0;
            *(float4*)(ob)     = make_float4(ov[0], ov[1], ov[2], ov[3]);
            *(float4*)(ob + 4) = make_float4(ov[4], ov[5], ov[6], ov[7]);
        }
        double v4[4] = {0.0, 0.0, 0.0, 0.0};
#pragma unroll
        for (int c = 0; c < 8; ++c) {
            double cd = (double)cv[c], id = (double)iv[c];
            v4[0] += cd; v4[1] += cd * cd;
            v4[2] += id; v4[3] += id * id;
        }
        block_reduce_d<4>(v4, s_red);
        const double muc = v4[0] * (1.0 / DM);
        const double rsc = 1.0 / sqrt(v4[1] * (1.0 / DM) - muc * muc + EPSD);
        const double mui = v4[2] * (1.0 / DM);
        const double rsi = 1.0 / sqrt(v4[3] * (1.0 / DM) - mui * mui + EPSD);
        float lc[8], ln_[8];
#pragma unroll
        for (int c = 0; c < 8; ++c) {
            const int d = d0 + c;
            lc[c]  = (float)((((double)cv[c] - muc) * rsc) * (double)lng[4 * DM + d] + (double)lnb[4 * DM + d]);
            ln_[c] = (float)((((double)iv[c] - mui) * rsi) * (double)lng[5 * DM + d] + (double)lnb[5 * DM + d]);
        }
        float* pc = g_lnct + (size_t)row * DM + d0;
        float* pn = g_lni + (size_t)row * DM + d0;
        *(float4*)(pc)     = make_float4(lc[0], lc[1], lc[2], lc[3]);
        *(float4*)(pc + 4) = make_float4(lc[4], lc[5], lc[6], lc[7]);
        *(float4*)(pn)     = make_float4(ln_[0], ln_[1], ln_[2], ln_[3]);
        *(float4*)(pn + 4) = make_float4(ln_[4], ln_[5], ln_[6], ln_[7]);
    }
}

// ---------------- kernel: SEQUENTIAL ascending-row fp32 column sums ---------
__global__ __launch_bounds__(32) void k_redsum() {
    const int d = blockIdx.x * 32 + threadIdx.x;
    const float* pc = g_lnct + d;
    const float* pn = g_lni + d;
    float ac = 0.0f, an = 0.0f;
#pragma unroll 16
    for (int row = 0; row < MROWS; ++row) {
        ac = __fadd_rn(ac, __ldg(pc + (size_t)row * DM));
        an = __fadd_rn(an, __ldg(pn + (size_t)row * DM));
    }
    const float cm = __fmul_rn(ac, 1.0f / MROWS);
    const float nm = __fmul_rn(an, 1.0f / MROWS);
    g_ratio[d] = __fdiv_rn(cm, nm);
}

// ---------------- kernel: ht pass (non-amplified; fp64 stats) ----------------
__global__ __launch_bounds__(512) void k_pass3(const float* __restrict__ lng,
                                               const float* __restrict__ lnb) {
    __shared__ double s_htm[DM];
    __shared__ double s_red[16 * 2];
    const int tid = threadIdx.x;
    for (int d = tid; d < DM; d += 512) s_htm[d] = 0.0;
    __syncthreads();
    const int d0 = tid * 8;
    float rr[8];
#pragma unroll
    for (int c = 0; c < 8; ++c) rr[c] = g_ratio[d0 + c];

    for (int row = blockIdx.x; row < MROWS; row += gridDim.x) {
        const float* ob = g_obuf + (size_t)row * DM + d0;
        float4 u = *(const float4*)(ob);
        float4 v = *(const float4*)(ob + 4);
        float h[8] = {__fmul_rn(u.x, rr[0]), __fmul_rn(u.y, rr[1]),
                      __fmul_rn(u.z, rr[2]), __fmul_rn(u.w, rr[3]),
                      __fmul_rn(v.x, rr[4]), __fmul_rn(v.y, rr[5]),
                      __fmul_rn(v.z, rr[6]), __fmul_rn(v.w, rr[7])};
        double v2[2] = {0.0, 0.0};
#pragma unroll
        for (int c = 0; c < 8; ++c) { double hd = (double)h[c]; v2[0] += hd; v2[1] += hd * hd; }
        block_reduce_d<2>(v2, s_red);
        const double mu = v2[0] * (1.0 / DM);
        const double rs = 1.0 / sqrt(v2[1] * (1.0 / DM) - mu * mu + EPSD);
#pragma unroll
        for (int c = 0; c < 8; ++c) {
            const int d = d0 + c;
            s_htm[d] += ((double)h[c] - mu) * rs * (double)lng[6 * DM + d] + (double)lnb[6 * DM + d];
        }
    }
    __syncthreads();
    for (int d = tid; d < DM; d += 512) atomicAdd(&g_htmsum[d], s_htm[d]);
}

// ---------------- kernel: slstm_out = LN(mean ht) (fp64) ----------------
__global__ __launch_bounds__(512) void k_pass4(const float* __restrict__ lng,
                                               const float* __restrict__ lnb) {
    __shared__ double s_red[16 * 2];
    const int tid = threadIdx.x;
    const int d0 = tid * 8;
    double h[8];
#pragma unroll
    for (int c = 0; c < 8; ++c) h[c] = g_htmsum[d0 + c] * (1.0 / MROWS);
    double v2[2] = {0.0, 0.0};
#pragma unroll
    for (int c = 0; c < 8; ++c) { v2[0] += h[c]; v2[1] += h[c] * h[c]; }
    block_reduce_d<2>(v2, s_red);
    const double mu = v2[0] * (1.0 / DM);
    const double rs = 1.0 / sqrt(v2[1] * (1.0 / DM) - mu * mu + EPSD);
#pragma unroll
    for (int c = 0; c < 8; ++c) {
        const int d = d0 + c;
        g_s[d] = (h[c] - mu) * rs * (double)lng[7 * DM + d] + (double)lnb[7 * DM + d];
    }
}

// ---------------- kernel: left/right GEMVs + gelu + product (fp64) ----------
__global__ __launch_bounds__(128) void k_pass5(const float* __restrict__ Wl,
                                               const float* __restrict__ bl,
                                               const float* __restrict__ Wr,
                                               const float* __restrict__ br) {
    __shared__ double s_red[4 * 2];
    const int j = blockIdx.x;
    const int tid = threadIdx.x;
    double v2[2] = {0.0, 0.0};
    const float* wl = Wl + (size_t)j * DM;
    const float* wr = Wr + (size_t)j * DM;
    for (int d = tid; d < DM; d += 128) {
        const double s = g_s[d];
        v2[0] += s * (double)wl[d];
        v2[1] += s * (double)wr[d];
    }
    block_reduce_d<2>(v2, s_red);
    if (tid == 0) {
        const double left = v2[0] + (double)bl[j];
        double right = v2[1] + (double)br[j];
        right = 0.5 * right * (1.0 + erf(right * 0.7071067811865475244));  // exact gelu
        g_v[j] = left * right;
    }
}

// ---------------- kernel: LN over DFF (fp64) ----------------
__global__ __launch_bounds__(512) void k_pass6a(const float* __restrict__ og,
                                                const float* __restrict__ ob) {
    __shared__ double s_red[16 * 2];
    const int tid = threadIdx.x;
    double v2[2] = {0.0, 0.0};
    for (int jj = tid; jj < DFF; jj += 512) {
        const double x = g_v[jj];
        v2[0] += x; v2[1] += x * x;
    }
    block_reduce_d<2>(v2, s_red);
    const double mu = v2[0] * (1.0 / DFF);
    const double rs = 1.0 / sqrt(v2[1] * (1.0 / DFF) - mu * mu + EPSD);
    for (int jj = tid; jj < DFF; jj += 512)
        g_u[jj] = (g_v[jj] - mu) * rs * (double)og[jj] + (double)ob[jj];
}

// ---------------- kernel: final projection GEMV (fp64) ----------------
__global__ __launch_bounds__(128) void k_pass6b(const float* __restrict__ Wp,
                                                const float* __restrict__ bp,
                                                float* __restrict__ out) {
    __shared__ double s_red[4 * 1];
    const int d = blockIdx.x;
    const int tid = threadIdx.x;
    double acc[1] = {0.0};
    const float* wp = Wp + (size_t)d * DFF;
    for (int jj = tid; jj < DFF; jj += 128) acc[0] += g_u[jj] * (double)wp[jj];
    block_reduce_d<1>(acc, s_red);
    if (tid == 0) out[d] = (float)(acc[0] + (double)bp[d]);
}

// ---------------- launcher ----------------
extern "C" void kernel_launch(void* const* d_in, const int* in_sizes, int n_in,
                              void* d_out, int out_size) {
    const float* x      = (const float*)d_in[0];
    const float* Wg     = (const float*)d_in[1];
    const float* bgates = (const float*)d_in[2];
    // d_in[3] = Wr_gates: multiplies zero initial state -> unused
    const float* lng    = (const float*)d_in[4];
    const float* lnb    = (const float*)d_in[5];
    const float* lnoutg = (const float*)d_in[6];
    const float* lnoutb = (const float*)d_in[7];
    const float* Wl     = (const float*)d_in[8];
    const float* bl     = (const float*)d_in[9];
    const float* Wr     = (const float*)d_in[10];
    const float* br     = (const float*)d_in[11];
    const float* Wp     = (const float*)d_in[12];
    const float* bp     = (const float*)d_in[13];
    float* out = (float*)d_out;

    k_zero<<<8, 512>>>();
    k_silu<<<(MROWS * (size_t)DM) / (256 * 4), 256>>>(x);
    k_gemm_oz<<<dim3(64, 8, 8), 512>>>(Wg);   // gates o,z — TF32, 2x occupancy
    k_gemm_if<<<dim3(64, 8, 8), 256>>>(Wg);   // gates i,f — bit-exact scalar
    k_pass2<<<296, 512>>>(bgates, lng, lnb);
    k_redsum<<<DM / 32, 32>>>();
    k_pass3<<<296, 512>>>(lng, lnb);
    k_pass4<<<1, 512>>>(lng, lnb);
    k_pass5<<<DFF, 128>>>(Wl, bl, Wr, br);
    k_pass6a<<<1, 512>>>(lnoutg, lnoutb);
    k_pass6b<<<DM, 128>>>(Wp, bp, out);
}

// round 15
// speedup vs baseline: 1.6156x; 1.0093x over previous
#include <cuda_runtime.h>
#include <math.h>
#include <stdint.h>

// ---------------- problem constants ----------------
#define DM      4096
#define MROWS   8192          // B*N = 4*2048
#define IB      1024          // block size (DM / 4 blocks)
#define DFF     5461
#define EPSD    1e-5

typedef unsigned long long u64;

// ---------------- scratch (device globals; no allocations allowed) ----------
__device__ float  g_xa[(size_t)MROWS * DM];        // 128 MB silu(x)
__device__ float  g_pre[4ULL * MROWS * DM];        // 512 MB gate pre-activations
__device__ float  g_lnct[(size_t)MROWS * DM];      // 128 MB LN(i*z) values
__device__ float  g_lni[(size_t)MROWS * DM];       // 128 MB LN(i) values
__device__ float  g_obuf[(size_t)MROWS * DM];      // 128 MB o-gate values
__device__ float  g_ratio[DM];                     // ct/nt (fp32, ref-matched)
__device__ double g_htmsum[DM];
__device__ double g_s[DM];                         // slstm_out
__device__ double g_v[DFF];                        // left*right (pre-LN)
__device__ double g_u[DFF];                        // LN'd

// ---------------- XLA-matched elementwise math ----------------
__device__ __forceinline__ float tanh_xla(float x) {
    const float kMax = 7.90531110763549805f;
    float cx = fminf(fmaxf(x, -kMax), kMax);
    float x2 = __fmul_rn(cx, cx);
    float p = fmaf(x2, -2.76076847742355e-16f, 2.00018790482477e-13f);
    p = fmaf(p, x2, -8.60467152213735e-11f);
    p = fmaf(p, x2, 5.12229709037114e-08f);
    p = fmaf(p, x2, 1.48572235717979e-05f);
    p = fmaf(p, x2, 6.37261928875436e-04f);
    p = fmaf(p, x2, 4.89352455891786e-03f);
    p = __fmul_rn(cx, p);
    float q = fmaf(x2, 1.19825839466702e-06f, 1.18534705686654e-04f);
    q = fmaf(q, x2, 2.26843463243900e-03f);
    q = fmaf(q, x2, 4.89352518554385e-03f);
    float r = __fdiv_rn(p, q);
    return (fabsf(x) < 0.0004f) ? x : r;
}

__device__ __forceinline__ float logistic_xla(float x) {
    return fmaf(0.5f, tanh_xla(__fmul_rn(0.5f, x)), 0.5f);
}

__device__ __forceinline__ float silu_xla(float x) {
    return __fmul_rn(x, logistic_xla(x));
}

// ---------------- TF32 helpers ----------------
__device__ __forceinline__ float to_tf32(float v) {
    unsigned u;
    asm("cvt.rna.tf32.f32 %0, %1;" : "=r"(u) : "f"(v));
    return __uint_as_float(u);
}

__device__ __forceinline__ void mma_tf32(float4& d, const float* a, float b0, float b1) {
    asm volatile(
        "mma.sync.aligned.m16n8k8.row.col.f32.tf32.tf32.f32 "
        "{%0,%1,%2,%3}, {%4,%5,%6,%7}, {%8,%9}, {%0,%1,%2,%3};\n"
        : "+f"(d.x), "+f"(d.y), "+f"(d.z), "+f"(d.w)
        : "r"(__float_as_uint(a[0])), "r"(__float_as_uint(a[1])),
          "r"(__float_as_uint(a[2])), "r"(__float_as_uint(a[3])),
          "r"(__float_as_uint(b0)), "r"(__float_as_uint(b1)));
}

// ---------------- packed fp32 FMA (Blackwell f32x2; each half is rn-exact) --
__device__ __forceinline__ void ffma2(u64& d, u64 a, u64 b) {
    asm("fma.rn.f32x2 %0, %1, %2, %0;" : "+l"(d) : "l"(a), "l"(b));
}
__device__ __forceinline__ u64 splat2(float v) {
    u64 r;
    asm("mov.b64 %0, {%1, %1};" : "=l"(r) : "f"(v));
    return r;
}
__device__ __forceinline__ void unpack2(u64 v, float& lo, float& hi) {
    asm("mov.b64 {%0, %1}, %2;" : "=f"(lo), "=f"(hi) : "l"(v));
}

// ---------------- fp64 block reduce ----------------
template <int NV>
__device__ __forceinline__ void block_reduce_d(double* v, double* sred) {
    const int lane = threadIdx.x & 31;
    const int wid  = threadIdx.x >> 5;
    const int nw   = (blockDim.x + 31) >> 5;
#pragma unroll
    for (int i = 0; i < NV; ++i) {
        double x = v[i];
#pragma unroll
        for (int o = 16; o > 0; o >>= 1) x += __shfl_xor_sync(0xffffffffu, x, o);
        v[i] = x;
    }
    __syncthreads();
    if (lane == 0) {
#pragma unroll
        for (int i = 0; i < NV; ++i) sred[wid * NV + i] = v[i];
    }
    __syncthreads();
    if (wid == 0) {
#pragma unroll
        for (int i = 0; i < NV; ++i) {
            double x = (lane < nw) ? sred[lane * NV + i] : 0.0;
#pragma unroll
            for (int o = 16; o > 0; o >>= 1) x += __shfl_xor_sync(0xffffffffu, x, o);
            if (lane == 0) sred[i] = x;
        }
    }
    __syncthreads();
#pragma unroll
    for (int i = 0; i < NV; ++i) v[i] = sred[i];
    __syncthreads();
}

// ---------------- kernel: zero + silu ----------------
__global__ void k_zero() {
    int idx = blockIdx.x * blockDim.x + threadIdx.x;
    if (idx < DM) g_htmsum[idx] = 0.0;
}

__global__ __launch_bounds__(256) void k_silu(const float* __restrict__ x) {
    size_t i = ((size_t)blockIdx.x * 256 + threadIdx.x) * 4;
    float4 v = *(const float4*)(x + i);
    v.x = silu_xla(v.x); v.y = silu_xla(v.y); v.z = silu_xla(v.z); v.w = silu_xla(v.w);
    *(float4*)(g_xa + i) = v;
}

// ---------------- kernel: FFMA2 fp32 SGEMM (gates i,f), ascending-k --------
// Bit-exact to scalar fmaf chains: each f32x2 half is an independent rn FMA;
// pairing is across output columns only (same per-element k order).
// 512 threads, 1 CTA/SM (no 128-reg cap -> no spills, unlike R6).
// warp = 8-row group (A loads warp-uniform broadcasts); lane = 4-col group
// (B loaded as native u64 via LDS.64 -> zero pack cost for B).
__global__ __launch_bounds__(512, 1) void k_gemm_if(const float* __restrict__ Wg) {
    __shared__ __align__(16) float As[2][16 * 132];
    __shared__ __align__(16) float Bs[2][16 * 132];

    const int mtile = blockIdx.x;
    const int ntile = blockIdx.y;
    const int g     = blockIdx.z & 1;        // gate 0 or 1
    const int blk   = blockIdx.z >> 1;

    const int tid  = threadIdx.x;
    const int w    = tid >> 5;               // 0..15 -> row group
    const int lane = tid & 31;               // -> col group
    const int rb   = w * 8;
    const int cb   = lane * 4;

    const float* aBase = g_xa + (size_t)(mtile * 128) * DM + blk * IB;
    const float* bBase = Wg + ((size_t)(g * 4 + blk)) * IB * IB + (size_t)(ntile * 128) * IB;

    const int ar = tid >> 2;                 // 0..127
    const int aq = (tid & 3) * 4;            // 0,4,8,12

    u64 acc[8][2];
#pragma unroll
    for (int i = 0; i < 8; ++i) { acc[i][0] = 0ull; acc[i][1] = 0ull; }

    float4 pa, pb;
    pa = *(const float4*)(aBase + (size_t)ar * DM + aq);
    pb = *(const float4*)(bBase + (size_t)ar * IB + aq);
    {
        float* A = As[0]; float* B = Bs[0];
        A[(aq + 0) * 132 + ar] = pa.x; A[(aq + 1) * 132 + ar] = pa.y;
        A[(aq + 2) * 132 + ar] = pa.z; A[(aq + 3) * 132 + ar] = pa.w;
        B[(aq + 0) * 132 + ar] = pb.x; B[(aq + 1) * 132 + ar] = pb.y;
        B[(aq + 2) * 132 + ar] = pb.z; B[(aq + 3) * 132 + ar] = pb.w;
    }
    __syncthreads();

#pragma unroll 1
    for (int kt = 0; kt < 64; ++kt) {
        const int cur = kt & 1;
        if (kt < 63) {
            const int k0 = (kt + 1) * 16;
            pa = *(const float4*)(aBase + (size_t)ar * DM + k0 + aq);
            pb = *(const float4*)(bBase + (size_t)ar * IB + k0 + aq);
        }
        const float* A = As[cur];
        const float* B = Bs[cur];
#pragma unroll
        for (int k = 0; k < 16; ++k) {
            float4 a0 = *(const float4*)(A + k * 132 + rb);      // warp-uniform
            float4 a1 = *(const float4*)(A + k * 132 + rb + 4);  // warp-uniform
            u64 b0 = *(const u64*)(B + k * 132 + cb);            // cols cb, cb+1
            u64 b1 = *(const u64*)(B + k * 132 + cb + 2);        // cols cb+2, cb+3
            u64 as_[8];
            as_[0] = splat2(a0.x); as_[1] = splat2(a0.y);
            as_[2] = splat2(a0.z); as_[3] = splat2(a0.w);
            as_[4] = splat2(a1.x); as_[5] = splat2(a1.y);
            as_[6] = splat2(a1.z); as_[7] = splat2(a1.w);
#pragma unroll
            for (int i = 0; i < 8; ++i) {
                ffma2(acc[i][0], as_[i], b0);
                ffma2(acc[i][1], as_[i], b1);
            }
        }
        if (kt < 63) {
            float* An = As[cur ^ 1]; float* Bn = Bs[cur ^ 1];
            An[(aq + 0) * 132 + ar] = pa.x; An[(aq + 1) * 132 + ar] = pa.y;
            An[(aq + 2) * 132 + ar] = pa.z; An[(aq + 3) * 132 + ar] = pa.w;
            Bn[(aq + 0) * 132 + ar] = pb.x; Bn[(aq + 1) * 132 + ar] = pb.y;
            Bn[(aq + 2) * 132 + ar] = pb.z; Bn[(aq + 3) * 132 + ar] = pb.w;
            __syncthreads();
        }
    }

    float* C = g_pre + (size_t)g * MROWS * DM + (size_t)blk * IB + (size_t)(ntile * 128) + cb;
#pragma unroll
    for (int i = 0; i < 8; ++i) {
        const size_t row = (size_t)(mtile * 128 + rb + i);
        float c0, c1, c2, c3;
        unpack2(acc[i][0], c0, c1);
        unpack2(acc[i][1], c2, c3);
        *(float4*)(C + row * DM) = make_float4(c0, c1, c2, c3);
    }
}

// ---------------- kernel: single-term TF32 MMA GEMM (gates o,z) ------------
// (R8 version, proven fastest for oz: 256 threads, [k][n] stride-136 layout,
//  tf32 convert at smem store, register-prefetch double buffer, 1 sync/tile.)
__global__ __launch_bounds__(256, 2) void k_gemm_oz(const float* __restrict__ Wg) {
    __shared__ __align__(16) float As[2][16 * 136];
    __shared__ __align__(16) float Bs[2][16 * 136];

    const int mtile = blockIdx.x;
    const int ntile = blockIdx.y;
    const int g     = 2 + (blockIdx.z & 1);  // gate 2 or 3
    const int blk   = blockIdx.z >> 1;

    const int tid  = threadIdx.x;
    const int lane = tid & 31;
    const int wid  = tid >> 5;
    const int gid  = lane >> 2;
    const int tig  = lane & 3;
    const int warp_m = wid >> 2;             // 0..1
    const int warp_n = wid & 3;              // 0..3

    const float* aBase = g_xa + (size_t)(mtile * 128) * DM + blk * IB;
    const float* bBase = Wg + ((size_t)(g * 4 + blk)) * IB * IB + (size_t)(ntile * 128) * IB;

    const int s0 = tid, s1 = tid + 256;
    const int ar0 = s0 >> 2, aq0 = (s0 & 3) * 4;
    const int ar1 = s1 >> 2, aq1 = (s1 & 3) * 4;

    float4 acc[4][4];
#pragma unroll
    for (int mi = 0; mi < 4; ++mi)
#pragma unroll
        for (int ni = 0; ni < 4; ++ni) acc[mi][ni] = make_float4(0.f, 0.f, 0.f, 0.f);

    float4 pa0, pa1, pb0, pb1;
    pa0 = *(const float4*)(aBase + (size_t)ar0 * DM + aq0);
    pa1 = *(const float4*)(aBase + (size_t)ar1 * DM + aq1);
    pb0 = *(const float4*)(bBase + (size_t)ar0 * IB + aq0);
    pb1 = *(const float4*)(bBase + (size_t)ar1 * IB + aq1);
    {
        float* A = As[0]; float* B = Bs[0];
        A[(aq0 + 0) * 136 + ar0] = to_tf32(pa0.x); A[(aq0 + 1) * 136 + ar0] = to_tf32(pa0.y);
        A[(aq0 + 2) * 136 + ar0] = to_tf32(pa0.z); A[(aq0 + 3) * 136 + ar0] = to_tf32(pa0.w);
        A[(aq1 + 0) * 136 + ar1] = to_tf32(pa1.x); A[(aq1 + 1) * 136 + ar1] = to_tf32(pa1.y);
        A[(aq1 + 2) * 136 + ar1] = to_tf32(pa1.z); A[(aq1 + 3) * 136 + ar1] = to_tf32(pa1.w);
        B[(aq0 + 0) * 136 + ar0] = to_tf32(pb0.x); B[(aq0 + 1) * 136 + ar0] = to_tf32(pb0.y);
        B[(aq0 + 2) * 136 + ar0] = to_tf32(pb0.z); B[(aq0 + 3) * 136 + ar0] = to_tf32(pb0.w);
        B[(aq1 + 0) * 136 + ar1] = to_tf32(pb1.x); B[(aq1 + 1) * 136 + ar1] = to_tf32(pb1.y);
        B[(aq1 + 2) * 136 + ar1] = to_tf32(pb1.z); B[(aq1 + 3) * 136 + ar1] = to_tf32(pb1.w);
    }
    __syncthreads();

#pragma unroll 1
    for (int kt = 0; kt < 64; ++kt) {
        const int cur = kt & 1;
        if (kt < 63) {
            const int k0 = (kt + 1) * 16;
            pa0 = *(const float4*)(aBase + (size_t)ar0 * DM + k0 + aq0);
            pa1 = *(const float4*)(aBase + (size_t)ar1 * DM + k0 + aq1);
            pb0 = *(const float4*)(bBase + (size_t)ar0 * IB + k0 + aq0);
            pb1 = *(const float4*)(bBase + (size_t)ar1 * IB + k0 + aq1);
        }
        const float* A = As[cur];
        const float* B = Bs[cur];
#pragma unroll
        for (int ks = 0; ks < 16; ks += 8) {
            float a_[4][4];
#pragma unroll
            for (int mi = 0; mi < 4; ++mi) {
                const int rm = warp_m * 64 + mi * 16 + gid;
                a_[mi][0] = A[(ks + tig) * 136 + rm];
                a_[mi][1] = A[(ks + tig) * 136 + rm + 8];
                a_[mi][2] = A[(ks + tig + 4) * 136 + rm];
                a_[mi][3] = A[(ks + tig + 4) * 136 + rm + 8];
            }
#pragma unroll
            for (int ni = 0; ni < 4; ++ni) {
                const int nb = warp_n * 32 + ni * 8 + gid;
                const float b0 = B[(ks + tig) * 136 + nb];
                const float b1 = B[(ks + tig + 4) * 136 + nb];
#pragma unroll
                for (int mi = 0; mi < 4; ++mi)
                    mma_tf32(acc[mi][ni], a_[mi], b0, b1);
            }
        }
        if (kt < 63) {
            float* An = As[cur ^ 1]; float* Bn = Bs[cur ^ 1];
            An[(aq0 + 0) * 136 + ar0] = to_tf32(pa0.x); An[(aq0 + 1) * 136 + ar0] = to_tf32(pa0.y);
            An[(aq0 + 2) * 136 + ar0] = to_tf32(pa0.z); An[(aq0 + 3) * 136 + ar0] = to_tf32(pa0.w);
            An[(aq1 + 0) * 136 + ar1] = to_tf32(pa1.x); An[(aq1 + 1) * 136 + ar1] = to_tf32(pa1.y);
            An[(aq1 + 2) * 136 + ar1] = to_tf32(pa1.z); An[(aq1 + 3) * 136 + ar1] = to_tf32(pa1.w);
            Bn[(aq0 + 0) * 136 + ar0] = to_tf32(pb0.x); Bn[(aq0 + 1) * 136 + ar0] = to_tf32(pb0.y);
            Bn[(aq0 + 2) * 136 + ar0] = to_tf32(pb0.z); Bn[(aq0 + 3) * 136 + ar0] = to_tf32(pb0.w);
            Bn[(aq1 + 0) * 136 + ar1] = to_tf32(pb1.x); Bn[(aq1 + 1) * 136 + ar1] = to_tf32(pb1.y);
            Bn[(aq1 + 2) * 136 + ar1] = to_tf32(pb1.z); Bn[(aq1 + 3) * 136 + ar1] = to_tf32(pb1.w);
            __syncthreads();
        }
    }

    float* C = g_pre + (size_t)g * MROWS * DM + (size_t)blk * IB;
#pragma unroll
    for (int mi = 0; mi < 4; ++mi) {
#pragma unroll
        for (int ni = 0; ni < 4; ++ni) {
            const int row = mtile * 128 + warp_m * 64 + mi * 16 + gid;
            const int col = ntile * 128 + warp_n * 32 + ni * 8 + tig * 2;
            *(float2*)(C + (size_t)row * DM + col) = make_float2(acc[mi][ni].x, acc[mi][ni].y);
            *(float2*)(C + (size_t)(row + 8) * DM + col) = make_float2(acc[mi][ni].z, acc[mi][ni].w);
        }
    }
}

// ---------------- kernel: row-wise gates (stats fp64, values fp32) ----------
__global__ __launch_bounds__(512) void k_pass2(const float* __restrict__ b_gates,
                                               const float* __restrict__ lng,
                                               const float* __restrict__ lnb) {
    __shared__ double s_red[16 * 8];
    const int tid = threadIdx.x;
    const int d0 = tid * 8;

    for (int row = blockIdx.x; row < MROWS; row += gridDim.x) {
        float p[4][8];
#pragma unroll
        for (int gg = 0; gg < 4; ++gg) {
            const float* base = g_pre + ((size_t)gg * MROWS + row) * DM + d0;
            float4 u = *(const float4*)(base);
            float4 v = *(const float4*)(base + 4);
            const float* bg = b_gates + gg * DM + d0;
            float4 w = *(const float4*)(bg);
            float4 y = *(const float4*)(bg + 4);
            p[gg][0] = __fadd_rn(u.x, w.x); p[gg][1] = __fadd_rn(u.y, w.y);
            p[gg][2] = __fadd_rn(u.z, w.z); p[gg][3] = __fadd_rn(u.w, w.w);
            p[gg][4] = __fadd_rn(v.x, y.x); p[gg][5] = __fadd_rn(v.y, y.y);
            p[gg][6] = __fadd_rn(v.z, y.z); p[gg][7] = __fadd_rn(v.w, y.w);
        }
        double v8[8];
#pragma unroll
        for (int gg = 0; gg < 4; ++gg) {
            double s = 0.0, q = 0.0;
#pragma unroll
            for (int c = 0; c < 8; ++c) {
                double pv = (double)p[gg][c];
                s += pv; q += pv * pv;
            }
            v8[2 * gg] = s; v8[2 * gg + 1] = q;
        }
        block_reduce_d<8>(v8, s_red);
        double mu[4], rs[4];
#pragma unroll
        for (int gg = 0; gg < 4; ++gg) {
            mu[gg] = v8[2 * gg] * (1.0 / DM);
            double var = v8[2 * gg + 1] * (1.0 / DM) - mu[gg] * mu[gg];
            rs[gg] = 1.0 / sqrt(var + EPSD);
        }
        float iv[8], cv[8], ov[8];
#pragma unroll
        for (int c = 0; c < 8; ++c) {
            const int d = d0 + c;
            float li = (float)((((double)p[0][c] - mu[0]) * rs[0]) * (double)lng[d]          + (double)lnb[d]);
            float lf = (float)((((double)p[1][c] - mu[1]) * rs[1]) * (double)lng[DM + d]     + (double)lnb[DM + d]);
            float lo = (float)((((double)p[2][c] - mu[2]) * rs[2]) * (double)lng[2 * DM + d] + (double)lnb[2 * DM + d]);
            float lz = (float)((((double)p[3][c] - mu[3]) * rs[3]) * (double)lng[3 * DM + d] + (double)lnb[3 * DM + d]);
            float m  = fmaxf(li, lf);
            float q  = __fadd_rn(li, -m);
            float ii = (float)exp((double)q);        // near-correctly-rounded f32 exp
            float zz = tanh_xla(lz);
            ov[c] = logistic_xla(lo);
            iv[c] = ii;
            cv[c] = __fmul_rn(ii, zz);
        }
        {
            float* ob = g_obuf + (size_t)row * DM + d0;
            *(float4*)(ob)     = make_float4(ov[0], ov[1], ov[2], ov[3]);
            *(float4*)(ob + 4) = make_float4(ov[4], ov[5], ov[6], ov[7]);
        }
        double v4[4] = {0.0, 0.0, 0.0, 0.0};
#pragma unroll
        for (int c = 0; c < 8; ++c) {
            double cd = (double)cv[c], id = (double)iv[c];
            v4[0] += cd; v4[1] += cd * cd;
            v4[2] += id; v4[3] += id * id;
        }
        block_reduce_d<4>(v4, s_red);
        const double muc = v4[0] * (1.0 / DM);
        const double rsc = 1.0 / sqrt(v4[1] * (1.0 / DM) - muc * muc + EPSD);
        const double mui = v4[2] * (1.0 / DM);
        const double rsi = 1.0 / sqrt(v4[3] * (1.0 / DM) - mui * mui + EPSD);
        float lc[8], ln_[8];
#pragma unroll
        for (int c = 0; c < 8; ++c) {
            const int d = d0 + c;
            lc[c]  = (float)((((double)cv[c] - muc) * rsc) * (double)lng[4 * DM + d] + (double)lnb[4 * DM + d]);
            ln_[c] = (float)((((double)iv[c] - mui) * rsi) * (double)lng[5 * DM + d] + (double)lnb[5 * DM + d]);
        }
        float* pc = g_lnct + (size_t)row * DM + d0;
        float* pn = g_lni + (size_t)row * DM + d0;
        *(float4*)(pc)     = make_float4(lc[0], lc[1], lc[2], lc[3]);
        *(float4*)(pc + 4) = make_float4(lc[4], lc[5], lc[6], lc[7]);
        *(float4*)(pn)     = make_float4(ln_[0], ln_[1], ln_[2], ln_[3]);
        *(float4*)(pn + 4) = make_float4(ln_[4], ln_[5], ln_[6], ln_[7]);
    }
}

// ---------------- kernel: SEQUENTIAL ascending-row fp32 column sums ---------
__global__ __launch_bounds__(32) void k_redsum() {
    const int d = blockIdx.x * 32 + threadIdx.x;
    const float* pc = g_lnct + d;
    const float* pn = g_lni + d;
    float ac = 0.0f, an = 0.0f;
#pragma unroll 16
    for (int row = 0; row < MROWS; ++row) {
        ac = __fadd_rn(ac, __ldg(pc + (size_t)row * DM));
        an = __fadd_rn(an, __ldg(pn + (size_t)row * DM));
    }
    const float cm = __fmul_rn(ac, 1.0f / MROWS);
    const float nm = __fmul_rn(an, 1.0f / MROWS);
    g_ratio[d] = __fdiv_rn(cm, nm);
}

// ---------------- kernel: ht pass (non-amplified; fp64 stats) ----------------
__global__ __launch_bounds__(512) void k_pass3(const float* __restrict__ lng,
                                               const float* __restrict__ lnb) {
    __shared__ double s_htm[DM];
    __shared__ double s_red[16 * 2];
    const int tid = threadIdx.x;
    for (int d = tid; d < DM; d += 512) s_htm[d] = 0.0;
    __syncthreads();
    const int d0 = tid * 8;
    float rr[8];
#pragma unroll
    for (int c = 0; c < 8; ++c) rr[c] = g_ratio[d0 + c];

    for (int row = blockIdx.x; row < MROWS; row += gridDim.x) {
        const float* ob = g_obuf + (size_t)row * DM + d0;
        float4 u = *(const float4*)(ob);
        float4 v = *(const float4*)(ob + 4);
        float h[8] = {__fmul_rn(u.x, rr[0]), __fmul_rn(u.y, rr[1]),
                      __fmul_rn(u.z, rr[2]), __fmul_rn(u.w, rr[3]),
                      __fmul_rn(v.x, rr[4]), __fmul_rn(v.y, rr[5]),
                      __fmul_rn(v.z, rr[6]), __fmul_rn(v.w, rr[7])};
        double v2[2] = {0.0, 0.0};
#pragma unroll
        for (int c = 0; c < 8; ++c) { double hd = (double)h[c]; v2[0] += hd; v2[1] += hd * hd; }
        block_reduce_d<2>(v2, s_red);
        const double mu = v2[0] * (1.0 / DM);
        const double rs = 1.0 / sqrt(v2[1] * (1.0 / DM) - mu * mu + EPSD);
#pragma unroll
        for (int c = 0; c < 8; ++c) {
            const int d = d0 + c;
            s_htm[d] += ((double)h[c] - mu) * rs * (double)lng[6 * DM + d] + (double)lnb[6 * DM + d];
        }
    }
    __syncthreads();
    for (int d = tid; d < DM; d += 512) atomicAdd(&g_htmsum[d], s_htm[d]);
}

// ---------------- kernel: slstm_out = LN(mean ht) (fp64) ----------------
__global__ __launch_bounds__(512) void k_pass4(const float* __restrict__ lng,
                                               const float* __restrict__ lnb) {
    __shared__ double s_red[16 * 2];
    const int tid = threadIdx.x;
    const int d0 = tid * 8;
    double h[8];
#pragma unroll
    for (int c = 0; c < 8; ++c) h[c] = g_htmsum[d0 + c] * (1.0 / MROWS);
    double v2[2] = {0.0, 0.0};
#pragma unroll
    for (int c = 0; c < 8; ++c) { v2[0] += h[c]; v2[1] += h[c] * h[c]; }
    block_reduce_d<2>(v2, s_red);
    const double mu = v2[0] * (1.0 / DM);
    const double rs = 1.0 / sqrt(v2[1] * (1.0 / DM) - mu * mu + EPSD);
#pragma unroll
    for (int c = 0; c < 8; ++c) {
        const int d = d0 + c;
        g_s[d] = (h[c] - mu) * rs * (double)lng[7 * DM + d] + (double)lnb[7 * DM + d];
    }
}

// ---------------- kernel: left/right GEMVs + gelu + product (fp64) ----------
__global__ __launch_bounds__(128) void k_pass5(const float* __restrict__ Wl,
                                               const float* __restrict__ bl,
                                               const float* __restrict__ Wr,
                                               const float* __restrict__ br) {
    __shared__ double s_red[4 * 2];
    const int j = blockIdx.x;
    const int tid = threadIdx.x;
    double v2[2] = {0.0, 0.0};
    const float* wl = Wl + (size_t)j * DM;
    const float* wr = Wr + (size_t)j * DM;
    for (int d = tid; d < DM; d += 128) {
        const double s = g_s[d];
        v2[0] += s * (double)wl[d];
        v2[1] += s * (double)wr[d];
    }
    block_reduce_d<2>(v2, s_red);
    if (tid == 0) {
        const double left = v2[0] + (double)bl[j];
        double right = v2[1] + (double)br[j];
        right = 0.5 * right * (1.0 + erf(right * 0.7071067811865475244));  // exact gelu
        g_v[j] = left * right;
    }
}

// ---------------- kernel: LN over DFF (fp64) ----------------
__global__ __launch_bounds__(512) void k_pass6a(const float* __restrict__ og,
                                                const float* __restrict__ ob) {
    __shared__ double s_red[16 * 2];
    const int tid = threadIdx.x;
    double v2[2] = {0.0, 0.0};
    for (int jj = tid; jj < DFF; jj += 512) {
        const double x = g_v[jj];
        v2[0] += x; v2[1] += x * x;
    }
    block_reduce_d<2>(v2, s_red);
    const double mu = v2[0] * (1.0 / DFF);
    const double rs = 1.0 / sqrt(v2[1] * (1.0 / DFF) - mu * mu + EPSD);
    for (int jj = tid; jj < DFF; jj += 512)
        g_u[jj] = (g_v[jj] - mu) * rs * (double)og[jj] + (double)ob[jj];
}

// ---------------- kernel: final projection GEMV (fp64) ----------------
__global__ __launch_bounds__(128) void k_pass6b(const float* __restrict__ Wp,
                                                const float* __restrict__ bp,
                                                float* __restrict__ out) {
    __shared__ double s_red[4 * 1];
    const int d = blockIdx.x;
    const int tid = threadIdx.x;
    double acc[1] = {0.0};
    const float* wp = Wp + (size_t)d * DFF;
    for (int jj = tid; jj < DFF; jj += 128) acc[0] += g_u[jj] * (double)wp[jj];
    block_reduce_d<1>(acc, s_red);
    if (tid == 0) out[d] = (float)(acc[0] + (double)bp[d]);
}

// ---------------- launcher ----------------
extern "C" void kernel_launch(void* const* d_in, const int* in_sizes, int n_in,
                              void* d_out, int out_size) {
    const float* x      = (const float*)d_in[0];
    const float* Wg     = (const float*)d_in[1];
    const float* bgates = (const float*)d_in[2];
    // d_in[3] = Wr_gates: multiplies zero initial state -> unused
    const float* lng    = (const float*)d_in[4];
    const float* lnb    = (const float*)d_in[5];
    const float* lnoutg = (const float*)d_in[6];
    const float* lnoutb = (const float*)d_in[7];
    const float* Wl     = (const float*)d_in[8];
    const float* bl     = (const float*)d_in[9];
    const float* Wr     = (const float*)d_in[10];
    const float* br     = (const float*)d_in[11];
    const float* Wp     = (const float*)d_in[12];
    const float* bp     = (const float*)d_in[13];
    float* out = (float*)d_out;

    k_zero<<<8, 512>>>();
    k_silu<<<(MROWS * (size_t)DM) / (256 * 4), 256>>>(x);
    k_gemm_oz<<<dim3(64, 8, 8), 256>>>(Wg);   // gates o,z — R8 TF32 (proven)
    k_gemm_if<<<dim3(64, 8, 8), 512>>>(Wg);   // gates i,f — FFMA2, no reg cap
    k_pass2<<<296, 512>>>(bgates, lng, lnb);
    k_redsum<<<DM / 32, 32>>>();
    k_pass3<<<296, 512>>>(lng, lnb);
    k_pass4<<<1, 512>>>(lng, lnb);
    k_pass5<<<DFF, 128>>>(Wl, bl, Wr, br);
    k_pass6a<<<1, 512>>>(lnoutg, lnoutb);
    k_pass6b<<<DM, 128>>>(Wp, bp, out);
}

// round 16
// speedup vs baseline: 1.6695x; 1.0333x over previous
#include <cuda_runtime.h>
#include <math.h>
#include <stdint.h>

// ---------------- problem constants ----------------
#define DM      4096
#define MROWS   8192          // B*N = 4*2048
#define IB      1024          // block size (DM / 4 blocks)
#define DFF     5461
#define EPSD    1e-5

// ---------------- scratch (device globals; no allocations allowed) ----------
__device__ float  g_xa[(size_t)MROWS * DM];        // 128 MB silu(x)
__device__ float  g_pre[4ULL * MROWS * DM];        // 512 MB gate pre-activations
__device__ float  g_lnct[(size_t)MROWS * DM];      // 128 MB LN(i*z) values
__device__ float  g_lni[(size_t)MROWS * DM];       // 128 MB LN(i) values
__device__ float  g_obuf[(size_t)MROWS * DM];      // 128 MB o-gate values
__device__ float  g_ratio[DM];                     // ct/nt (fp32, ref-matched)
__device__ double g_htmsum[DM];
__device__ double g_s[DM];                         // slstm_out
__device__ double g_v[DFF];                        // left*right (pre-LN)
__device__ double g_u[DFF];                        // LN'd

// ---------------- XLA-matched elementwise math ----------------
__device__ __forceinline__ float tanh_xla(float x) {
    const float kMax = 7.90531110763549805f;
    float cx = fminf(fmaxf(x, -kMax), kMax);
    float x2 = __fmul_rn(cx, cx);
    float p = fmaf(x2, -2.76076847742355e-16f, 2.00018790482477e-13f);
    p = fmaf(p, x2, -8.60467152213735e-11f);
    p = fmaf(p, x2, 5.12229709037114e-08f);
    p = fmaf(p, x2, 1.48572235717979e-05f);
    p = fmaf(p, x2, 6.37261928875436e-04f);
    p = fmaf(p, x2, 4.89352455891786e-03f);
    p = __fmul_rn(cx, p);
    float q = fmaf(x2, 1.19825839466702e-06f, 1.18534705686654e-04f);
    q = fmaf(q, x2, 2.26843463243900e-03f);
    q = fmaf(q, x2, 4.89352518554385e-03f);
    float r = __fdiv_rn(p, q);
    return (fabsf(x) < 0.0004f) ? x : r;
}

__device__ __forceinline__ float logistic_xla(float x) {
    return fmaf(0.5f, tanh_xla(__fmul_rn(0.5f, x)), 0.5f);
}

__device__ __forceinline__ float silu_xla(float x) {
    return __fmul_rn(x, logistic_xla(x));
}

// ---------------- TF32 helpers ----------------
__device__ __forceinline__ float to_tf32(float v) {
    unsigned u;
    asm("cvt.rna.tf32.f32 %0, %1;" : "=r"(u) : "f"(v));
    return __uint_as_float(u);
}

__device__ __forceinline__ void mma_tf32(float4& d, const float* a, float b0, float b1) {
    asm volatile(
        "mma.sync.aligned.m16n8k8.row.col.f32.tf32.tf32.f32 "
        "{%0,%1,%2,%3}, {%4,%5,%6,%7}, {%8,%9}, {%0,%1,%2,%3};\n"
        : "+f"(d.x), "+f"(d.y), "+f"(d.z), "+f"(d.w)
        : "r"(__float_as_uint(a[0])), "r"(__float_as_uint(a[1])),
          "r"(__float_as_uint(a[2])), "r"(__float_as_uint(a[3])),
          "r"(__float_as_uint(b0)), "r"(__float_as_uint(b1)));
}

// ---------------- fp64 block reduce ----------------
template <int NV>
__device__ __forceinline__ void block_reduce_d(double* v, double* sred) {
    const int lane = threadIdx.x & 31;
    const int wid  = threadIdx.x >> 5;
    const int nw   = (blockDim.x + 31) >> 5;
#pragma unroll
    for (int i = 0; i < NV; ++i) {
        double x = v[i];
#pragma unroll
        for (int o = 16; o > 0; o >>= 1) x += __shfl_xor_sync(0xffffffffu, x, o);
        v[i] = x;
    }
    __syncthreads();
    if (lane == 0) {
#pragma unroll
        for (int i = 0; i < NV; ++i) sred[wid * NV + i] = v[i];
    }
    __syncthreads();
    if (wid == 0) {
#pragma unroll
        for (int i = 0; i < NV; ++i) {
            double x = (lane < nw) ? sred[lane * NV + i] : 0.0;
#pragma unroll
            for (int o = 16; o > 0; o >>= 1) x += __shfl_xor_sync(0xffffffffu, x, o);
            if (lane == 0) sred[i] = x;
        }
    }
    __syncthreads();
#pragma unroll
    for (int i = 0; i < NV; ++i) v[i] = sred[i];
    __syncthreads();
}

// ---------------- kernel: zero + silu ----------------
__global__ void k_zero() {
    int idx = blockIdx.x * blockDim.x + threadIdx.x;
    if (idx < DM) g_htmsum[idx] = 0.0;
}

__global__ __launch_bounds__(256) void k_silu(const float* __restrict__ x) {
    size_t i = ((size_t)blockIdx.x * 256 + threadIdx.x) * 4;
    float4 v = *(const float4*)(x + i);
    v.x = silu_xla(v.x); v.y = silu_xla(v.y); v.z = silu_xla(v.z); v.w = silu_xla(v.w);
    *(float4*)(g_xa + i) = v;
}

// ---------------- kernel: scalar fp32 SGEMM (gates i,f), ascending-k -------
// Bit-exact match of XLA's sgemm chains (amplified denominator path). R8 form.
__global__ __launch_bounds__(256, 2) void k_gemm_if(const float* __restrict__ Wg) {
    __shared__ __align__(16) float As[2][16 * 132];
    __shared__ __align__(16) float Bs[2][16 * 132];

    const int mtile = blockIdx.x;
    const int ntile = blockIdx.y;
    const int g     = blockIdx.z & 1;        // gate 0 or 1
    const int blk   = blockIdx.z >> 1;

    const int tid = threadIdx.x;
    const int tx  = tid & 15;
    const int ty  = tid >> 4;
    const int rb  = ty * 8;
    const int nb1 = tx * 4;
    const int nb2 = 64 + tx * 4;

    const float* aBase = g_xa + (size_t)(mtile * 128) * DM + blk * IB;
    const float* bBase = Wg + ((size_t)(g * 4 + blk)) * IB * IB + (size_t)(ntile * 128) * IB;

    const int s0 = tid, s1 = tid + 256;
    const int ar0 = s0 >> 2, aq0 = (s0 & 3) * 4;
    const int ar1 = s1 >> 2, aq1 = (s1 & 3) * 4;

    float acc[8][8];
#pragma unroll
    for (int i = 0; i < 8; ++i)
#pragma unroll
        for (int j = 0; j < 8; ++j) acc[i][j] = 0.0f;

    float4 pa0, pa1, pb0, pb1;
    pa0 = *(const float4*)(aBase + (size_t)ar0 * DM + aq0);
    pa1 = *(const float4*)(aBase + (size_t)ar1 * DM + aq1);
    pb0 = *(const float4*)(bBase + (size_t)ar0 * IB + aq0);
    pb1 = *(const float4*)(bBase + (size_t)ar1 * IB + aq1);
    {
        float* A = As[0]; float* B = Bs[0];
        A[(aq0 + 0) * 132 + ar0] = pa0.x; A[(aq0 + 1) * 132 + ar0] = pa0.y;
        A[(aq0 + 2) * 132 + ar0] = pa0.z; A[(aq0 + 3) * 132 + ar0] = pa0.w;
        A[(aq1 + 0) * 132 + ar1] = pa1.x; A[(aq1 + 1) * 132 + ar1] = pa1.y;
        A[(aq1 + 2) * 132 + ar1] = pa1.z; A[(aq1 + 3) * 132 + ar1] = pa1.w;
        B[(aq0 + 0) * 132 + ar0] = pb0.x; B[(aq0 + 1) * 132 + ar0] = pb0.y;
        B[(aq0 + 2) * 132 + ar0] = pb0.z; B[(aq0 + 3) * 132 + ar0] = pb0.w;
        B[(aq1 + 0) * 132 + ar1] = pb1.x; B[(aq1 + 1) * 132 + ar1] = pb1.y;
        B[(aq1 + 2) * 132 + ar1] = pb1.z; B[(aq1 + 3) * 132 + ar1] = pb1.w;
    }
    __syncthreads();

#pragma unroll 1
    for (int kt = 0; kt < 64; ++kt) {
        const int cur = kt & 1;
        if (kt < 63) {
            const int k0 = (kt + 1) * 16;
            pa0 = *(const float4*)(aBase + (size_t)ar0 * DM + k0 + aq0);
            pa1 = *(const float4*)(aBase + (size_t)ar1 * DM + k0 + aq1);
            pb0 = *(const float4*)(bBase + (size_t)ar0 * IB + k0 + aq0);
            pb1 = *(const float4*)(bBase + (size_t)ar1 * IB + k0 + aq1);
        }
        const float* A = As[cur];
        const float* B = Bs[cur];
#pragma unroll
        for (int k = 0; k < 16; ++k) {
            float4 a0 = *(const float4*)(A + k * 132 + rb);
            float4 a1 = *(const float4*)(A + k * 132 + rb + 4);
            float4 b0 = *(const float4*)(B + k * 132 + nb1);
            float4 b1 = *(const float4*)(B + k * 132 + nb2);
            float av[8] = {a0.x, a0.y, a0.z, a0.w, a1.x, a1.y, a1.z, a1.w};
            float bv[8] = {b0.x, b0.y, b0.z, b0.w, b1.x, b1.y, b1.z, b1.w};
#pragma unroll
            for (int i = 0; i < 8; ++i)
#pragma unroll
                for (int j = 0; j < 8; ++j)
                    acc[i][j] = fmaf(av[i], bv[j], acc[i][j]);
        }
        if (kt < 63) {
            float* An = As[cur ^ 1]; float* Bn = Bs[cur ^ 1];
            An[(aq0 + 0) * 132 + ar0] = pa0.x; An[(aq0 + 1) * 132 + ar0] = pa0.y;
            An[(aq0 + 2) * 132 + ar0] = pa0.z; An[(aq0 + 3) * 132 + ar0] = pa0.w;
            An[(aq1 + 0) * 132 + ar1] = pa1.x; An[(aq1 + 1) * 132 + ar1] = pa1.y;
            An[(aq1 + 2) * 132 + ar1] = pa1.z; An[(aq1 + 3) * 132 + ar1] = pa1.w;
            Bn[(aq0 + 0) * 132 + ar0] = pb0.x; Bn[(aq0 + 1) * 132 + ar0] = pb0.y;
            Bn[(aq0 + 2) * 132 + ar0] = pb0.z; Bn[(aq0 + 3) * 132 + ar0] = pb0.w;
            Bn[(aq1 + 0) * 132 + ar1] = pb1.x; Bn[(aq1 + 1) * 132 + ar1] = pb1.y;
            Bn[(aq1 + 2) * 132 + ar1] = pb1.z; Bn[(aq1 + 3) * 132 + ar1] = pb1.w;
            __syncthreads();
        }
    }

    float* C = g_pre + (size_t)g * MROWS * DM + (size_t)blk * IB + (size_t)(ntile * 128);
#pragma unroll
    for (int i = 0; i < 8; ++i) {
        const size_t row = (size_t)(mtile * 128 + rb + i);
        *(float4*)(C + row * DM + nb1) = make_float4(acc[i][0], acc[i][1], acc[i][2], acc[i][3]);
        *(float4*)(C + row * DM + nb2) = make_float4(acc[i][4], acc[i][5], acc[i][6], acc[i][7]);
    }
}

// ---------------- kernel: single-term TF32 MMA GEMM (gates o,z) ------------
// (R8 version, proven fastest for oz.)
__global__ __launch_bounds__(256, 2) void k_gemm_oz(const float* __restrict__ Wg) {
    __shared__ __align__(16) float As[2][16 * 136];
    __shared__ __align__(16) float Bs[2][16 * 136];

    const int mtile = blockIdx.x;
    const int ntile = blockIdx.y;
    const int g     = 2 + (blockIdx.z & 1);  // gate 2 or 3
    const int blk   = blockIdx.z >> 1;

    const int tid  = threadIdx.x;
    const int lane = tid & 31;
    const int wid  = tid >> 5;
    const int gid  = lane >> 2;
    const int tig  = lane & 3;
    const int warp_m = wid >> 2;             // 0..1
    const int warp_n = wid & 3;              // 0..3

    const float* aBase = g_xa + (size_t)(mtile * 128) * DM + blk * IB;
    const float* bBase = Wg + ((size_t)(g * 4 + blk)) * IB * IB + (size_t)(ntile * 128) * IB;

    const int s0 = tid, s1 = tid + 256;
    const int ar0 = s0 >> 2, aq0 = (s0 & 3) * 4;
    const int ar1 = s1 >> 2, aq1 = (s1 & 3) * 4;

    float4 acc[4][4];
#pragma unroll
    for (int mi = 0; mi < 4; ++mi)
#pragma unroll
        for (int ni = 0; ni < 4; ++ni) acc[mi][ni] = make_float4(0.f, 0.f, 0.f, 0.f);

    float4 pa0, pa1, pb0, pb1;
    pa0 = *(const float4*)(aBase + (size_t)ar0 * DM + aq0);
    pa1 = *(const float4*)(aBase + (size_t)ar1 * DM + aq1);
    pb0 = *(const float4*)(bBase + (size_t)ar0 * IB + aq0);
    pb1 = *(const float4*)(bBase + (size_t)ar1 * IB + aq1);
    {
        float* A = As[0]; float* B = Bs[0];
        A[(aq0 + 0) * 136 + ar0] = to_tf32(pa0.x); A[(aq0 + 1) * 136 + ar0] = to_tf32(pa0.y);
        A[(aq0 + 2) * 136 + ar0] = to_tf32(pa0.z); A[(aq0 + 3) * 136 + ar0] = to_tf32(pa0.w);
        A[(aq1 + 0) * 136 + ar1] = to_tf32(pa1.x); A[(aq1 + 1) * 136 + ar1] = to_tf32(pa1.y);
        A[(aq1 + 2) * 136 + ar1] = to_tf32(pa1.z); A[(aq1 + 3) * 136 + ar1] = to_tf32(pa1.w);
        B[(aq0 + 0) * 136 + ar0] = to_tf32(pb0.x); B[(aq0 + 1) * 136 + ar0] = to_tf32(pb0.y);
        B[(aq0 + 2) * 136 + ar0] = to_tf32(pb0.z); B[(aq0 + 3) * 136 + ar0] = to_tf32(pb0.w);
        B[(aq1 + 0) * 136 + ar1] = to_tf32(pb1.x); B[(aq1 + 1) * 136 + ar1] = to_tf32(pb1.y);
        B[(aq1 + 2) * 136 + ar1] = to_tf32(pb1.z); B[(aq1 + 3) * 136 + ar1] = to_tf32(pb1.w);
    }
    __syncthreads();

#pragma unroll 1
    for (int kt = 0; kt < 64; ++kt) {
        const int cur = kt & 1;
        if (kt < 63) {
            const int k0 = (kt + 1) * 16;
            pa0 = *(const float4*)(aBase + (size_t)ar0 * DM + k0 + aq0);
            pa1 = *(const float4*)(aBase + (size_t)ar1 * DM + k0 + aq1);
            pb0 = *(const float4*)(bBase + (size_t)ar0 * IB + k0 + aq0);
            pb1 = *(const float4*)(bBase + (size_t)ar1 * IB + k0 + aq1);
        }
        const float* A = As[cur];
        const float* B = Bs[cur];
#pragma unroll
        for (int ks = 0; ks < 16; ks += 8) {
            float a_[4][4];
#pragma unroll
            for (int mi = 0; mi < 4; ++mi) {
                const int rm = warp_m * 64 + mi * 16 + gid;
                a_[mi][0] = A[(ks + tig) * 136 + rm];
                a_[mi][1] = A[(ks + tig) * 136 + rm + 8];
                a_[mi][2] = A[(ks + tig + 4) * 136 + rm];
                a_[mi][3] = A[(ks + tig + 4) * 136 + rm + 8];
            }
#pragma unroll
            for (int ni = 0; ni < 4; ++ni) {
                const int nb = warp_n * 32 + ni * 8 + gid;
                const float b0 = B[(ks + tig) * 136 + nb];
                const float b1 = B[(ks + tig + 4) * 136 + nb];
#pragma unroll
                for (int mi = 0; mi < 4; ++mi)
                    mma_tf32(acc[mi][ni], a_[mi], b0, b1);
            }
        }
        if (kt < 63) {
            float* An = As[cur ^ 1]; float* Bn = Bs[cur ^ 1];
            An[(aq0 + 0) * 136 + ar0] = to_tf32(pa0.x); An[(aq0 + 1) * 136 + ar0] = to_tf32(pa0.y);
            An[(aq0 + 2) * 136 + ar0] = to_tf32(pa0.z); An[(aq0 + 3) * 136 + ar0] = to_tf32(pa0.w);
            An[(aq1 + 0) * 136 + ar1] = to_tf32(pa1.x); An[(aq1 + 1) * 136 + ar1] = to_tf32(pa1.y);
            An[(aq1 + 2) * 136 + ar1] = to_tf32(pa1.z); An[(aq1 + 3) * 136 + ar1] = to_tf32(pa1.w);
            Bn[(aq0 + 0) * 136 + ar0] = to_tf32(pb0.x); Bn[(aq0 + 1) * 136 + ar0] = to_tf32(pb0.y);
            Bn[(aq0 + 2) * 136 + ar0] = to_tf32(pb0.z); Bn[(aq0 + 3) * 136 + ar0] = to_tf32(pb0.w);
            Bn[(aq1 + 0) * 136 + ar1] = to_tf32(pb1.x); Bn[(aq1 + 1) * 136 + ar1] = to_tf32(pb1.y);
            Bn[(aq1 + 2) * 136 + ar1] = to_tf32(pb1.z); Bn[(aq1 + 3) * 136 + ar1] = to_tf32(pb1.w);
            __syncthreads();
        }
    }

    float* C = g_pre + (size_t)g * MROWS * DM + (size_t)blk * IB;
#pragma unroll
    for (int mi = 0; mi < 4; ++mi) {
#pragma unroll
        for (int ni = 0; ni < 4; ++ni) {
            const int row = mtile * 128 + warp_m * 64 + mi * 16 + gid;
            const int col = ntile * 128 + warp_n * 32 + ni * 8 + tig * 2;
            *(float2*)(C + (size_t)row * DM + col) = make_float2(acc[mi][ni].x, acc[mi][ni].y);
            *(float2*)(C + (size_t)(row + 8) * DM + col) = make_float2(acc[mi][ni].z, acc[mi][ni].w);
        }
    }
}

// ---------------- kernel: row-wise gates (stats fp64, values fp32) ----------
__global__ __launch_bounds__(512) void k_pass2(const float* __restrict__ b_gates,
                                               const float* __restrict__ lng,
                                               const float* __restrict__ lnb) {
    __shared__ double s_red[16 * 8];
    const int tid = threadIdx.x;
    const int d0 = tid * 8;

    for (int row = blockIdx.x; row < MROWS; row += gridDim.x) {
        float p[4][8];
#pragma unroll
        for (int gg = 0; gg < 4; ++gg) {
            const float* base = g_pre + ((size_t)gg * MROWS + row) * DM + d0;
            float4 u = *(const float4*)(base);
            float4 v = *(const float4*)(base + 4);
            const float* bg = b_gates + gg * DM + d0;
            float4 w = *(const float4*)(bg);
            float4 y = *(const float4*)(bg + 4);
            p[gg][0] = __fadd_rn(u.x, w.x); p[gg][1] = __fadd_rn(u.y, w.y);
            p[gg][2] = __fadd_rn(u.z, w.z); p[gg][3] = __fadd_rn(u.w, w.w);
            p[gg][4] = __fadd_rn(v.x, y.x); p[gg][5] = __fadd_rn(v.y, y.y);
            p[gg][6] = __fadd_rn(v.z, y.z); p[gg][7] = __fadd_rn(v.w, y.w);
        }
        double v8[8];
#pragma unroll
        for (int gg = 0; gg < 4; ++gg) {
            double s = 0.0, q = 0.0;
#pragma unroll
            for (int c = 0; c < 8; ++c) {
                double pv = (double)p[gg][c];
                s += pv; q += pv * pv;
            }
            v8[2 * gg] = s; v8[2 * gg + 1] = q;
        }
        block_reduce_d<8>(v8, s_red);
        double mu[4], rs[4];
#pragma unroll
        for (int gg = 0; gg < 4; ++gg) {
            mu[gg] = v8[2 * gg] * (1.0 / DM);
            double var = v8[2 * gg + 1] * (1.0 / DM) - mu[gg] * mu[gg];
            rs[gg] = 1.0 / sqrt(var + EPSD);
        }
        float iv[8], cv[8], ov[8];
#pragma unroll
        for (int c = 0; c < 8; ++c) {
            const int d = d0 + c;
            float li = (float)((((double)p[0][c] - mu[0]) * rs[0]) * (double)lng[d]          + (double)lnb[d]);
            float lf = (float)((((double)p[1][c] - mu[1]) * rs[1]) * (double)lng[DM + d]     + (double)lnb[DM + d]);
            float lo = (float)((((double)p[2][c] - mu[2]) * rs[2]) * (double)lng[2 * DM + d] + (double)lnb[2 * DM + d]);
            float lz = (float)((((double)p[3][c] - mu[3]) * rs[3]) * (double)lng[3 * DM + d] + (double)lnb[3 * DM + d]);
            float m  = fmaxf(li, lf);
            float q  = __fadd_rn(li, -m);
            float ii = (float)exp((double)q);        // near-correctly-rounded f32 exp
            float zz = tanh_xla(lz);
            ov[c] = logistic_xla(lo);
            iv[c] = ii;
            cv[c] = __fmul_rn(ii, zz);
        }
        {
            float* ob = g_obuf + (size_t)row * DM + d0;
            *(float4*)(ob)     = make_float4(ov[0], ov[1], ov[2], ov[3]);
            *(float4*)(ob + 4) = make_float4(ov[4], ov[5], ov[6], ov[7]);
        }
        double v4[4] = {0.0, 0.0, 0.0, 0.0};
#pragma unroll
        for (int c = 0; c < 8; ++c) {
            double cd = (double)cv[c], id = (double)iv[c];
            v4[0] += cd; v4[1] += cd * cd;
            v4[2] += id; v4[3] += id * id;
        }
        block_reduce_d<4>(v4, s_red);
        const double muc = v4[0] * (1.0 / DM);
        const double rsc = 1.0 / sqrt(v4[1] * (1.0 / DM) - muc * muc + EPSD);
        const double mui = v4[2] * (1.0 / DM);
        const double rsi = 1.0 / sqrt(v4[3] * (1.0 / DM) - mui * mui + EPSD);
        float lc[8], ln_[8];
#pragma unroll
        for (int c = 0; c < 8; ++c) {
            const int d = d0 + c;
            lc[c]  = (float)((((double)cv[c] - muc) * rsc) * (double)lng[4 * DM + d] + (double)lnb[4 * DM + d]);
            ln_[c] = (float)((((double)iv[c] - mui) * rsi) * (double)lng[5 * DM + d] + (double)lnb[5 * DM + d]);
        }
        float* pc = g_lnct + (size_t)row * DM + d0;
        float* pn = g_lni + (size_t)row * DM + d0;
        *(float4*)(pc)     = make_float4(lc[0], lc[1], lc[2], lc[3]);
        *(float4*)(pc + 4) = make_float4(lc[4], lc[5], lc[6], lc[7]);
        *(float4*)(pn)     = make_float4(ln_[0], ln_[1], ln_[2], ln_[3]);
        *(float4*)(pn + 4) = make_float4(ln_[4], ln_[5], ln_[6], ln_[7]);
    }
}

// ---------------- kernel: smem-staged sequential fp32 column sums -----------
// Same ascending-row single-accumulator fp32 chains as before (bit-exact),
// but rows are staged into shared memory by 256 parallel threads first, so
// the dependent-add chain reads smem (prefetchable) instead of serialized
// global loads. Block = 32 d-columns; 64 chain-owner lanes (2 arrays x 32 d).
__global__ __launch_bounds__(256) void k_redsum() {
    __shared__ float s_c[128][33];
    __shared__ float s_n[128][33];
    __shared__ float s_fin[64];
    const int d0  = blockIdx.x * 32;
    const int tid = threadIdx.x;

    float ac = 0.0f, an = 0.0f;
#pragma unroll 1
    for (int chunk = 0; chunk < MROWS / 128; ++chunk) {
        const int rbase = chunk * 128;
#pragma unroll
        for (int t = tid; t < 128 * 32; t += 256) {
            const int r = t >> 5, d = t & 31;
            s_c[r][d] = g_lnct[(size_t)(rbase + r) * DM + d0 + d];
            s_n[r][d] = g_lni [(size_t)(rbase + r) * DM + d0 + d];
        }
        __syncthreads();
        if (tid < 32) {
#pragma unroll 8
            for (int r = 0; r < 128; ++r) ac = __fadd_rn(ac, s_c[r][tid]);
        } else if (tid < 64) {
            const int d = tid - 32;
#pragma unroll 8
            for (int r = 0; r < 128; ++r) an = __fadd_rn(an, s_n[r][d]);
        }
        __syncthreads();
    }
    if (tid < 64) s_fin[tid] = (tid < 32) ? ac : an;
    __syncthreads();
    if (tid < 32) {
        const float cm = __fmul_rn(s_fin[tid], 1.0f / MROWS);
        const float nm = __fmul_rn(s_fin[tid + 32], 1.0f / MROWS);
        g_ratio[d0 + tid] = __fdiv_rn(cm, nm);
    }
}

// ---------------- kernel: ht pass (non-amplified; fp64 stats) ----------------
__global__ __launch_bounds__(512) void k_pass3(const float* __restrict__ lng,
                                               const float* __restrict__ lnb) {
    __shared__ double s_htm[DM];
    __shared__ double s_red[16 * 2];
    const int tid = threadIdx.x;
    for (int d = tid; d < DM; d += 512) s_htm[d] = 0.0;
    __syncthreads();
    const int d0 = tid * 8;
    float rr[8];
#pragma unroll
    for (int c = 0; c < 8; ++c) rr[c] = g_ratio[d0 + c];

    for (int row = blockIdx.x; row < MROWS; row += gridDim.x) {
        const float* ob = g_obuf + (size_t)row * DM + d0;
        float4 u = *(const float4*)(ob);
        float4 v = *(const float4*)(ob + 4);
        float h[8] = {__fmul_rn(u.x, rr[0]), __fmul_rn(u.y, rr[1]),
                      __fmul_rn(u.z, rr[2]), __fmul_rn(u.w, rr[3]),
                      __fmul_rn(v.x, rr[4]), __fmul_rn(v.y, rr[5]),
                      __fmul_rn(v.z, rr[6]), __fmul_rn(v.w, rr[7])};
        double v2[2] = {0.0, 0.0};
#pragma unroll
        for (int c = 0; c < 8; ++c) { double hd = (double)h[c]; v2[0] += hd; v2[1] += hd * hd; }
        block_reduce_d<2>(v2, s_red);
        const double mu = v2[0] * (1.0 / DM);
        const double rs = 1.0 / sqrt(v2[1] * (1.0 / DM) - mu * mu + EPSD);
#pragma unroll
        for (int c = 0; c < 8; ++c) {
            const int d = d0 + c;
            s_htm[d] += ((double)h[c] - mu) * rs * (double)lng[6 * DM + d] + (double)lnb[6 * DM + d];
        }
    }
    __syncthreads();
    for (int d = tid; d < DM; d += 512) atomicAdd(&g_htmsum[d], s_htm[d]);
}

// ---------------- kernel: slstm_out = LN(mean ht) (fp64) ----------------
__global__ __launch_bounds__(512) void k_pass4(const float* __restrict__ lng,
                                               const float* __restrict__ lnb) {
    __shared__ double s_red[16 * 2];
    const int tid = threadIdx.x;
    const int d0 = tid * 8;
    double h[8];
#pragma unroll
    for (int c = 0; c < 8; ++c) h[c] = g_htmsum[d0 + c] * (1.0 / MROWS);
    double v2[2] = {0.0, 0.0};
#pragma unroll
    for (int c = 0; c < 8; ++c) { v2[0] += h[c]; v2[1] += h[c] * h[c]; }
    block_reduce_d<2>(v2, s_red);
    const double mu = v2[0] * (1.0 / DM);
    const double rs = 1.0 / sqrt(v2[1] * (1.0 / DM) - mu * mu + EPSD);
#pragma unroll
    for (int c = 0; c < 8; ++c) {
        const int d = d0 + c;
        g_s[d] = (h[c] - mu) * rs * (double)lng[7 * DM + d] + (double)lnb[7 * DM + d];
    }
}

// ---------------- kernel: left/right GEMVs + gelu + product (fp64) ----------
__global__ __launch_bounds__(128) void k_pass5(const float* __restrict__ Wl,
                                               const float* __restrict__ bl,
                                               const float* __restrict__ Wr,
                                               const float* __restrict__ br) {
    __shared__ double s_red[4 * 2];
    const int j = blockIdx.x;
    const int tid = threadIdx.x;
    double v2[2] = {0.0, 0.0};
    const float* wl = Wl + (size_t)j * DM;
    const float* wr = Wr + (size_t)j * DM;
    for (int d = tid; d < DM; d += 128) {
        const double s = g_s[d];
        v2[0] += s * (double)wl[d];
        v2[1] += s * (double)wr[d];
    }
    block_reduce_d<2>(v2, s_red);
    if (tid == 0) {
        const double left = v2[0] + (double)bl[j];
        double right = v2[1] + (double)br[j];
        right = 0.5 * right * (1.0 + erf(right * 0.7071067811865475244));  // exact gelu
        g_v[j] = left * right;
    }
}

// ---------------- kernel: LN over DFF (fp64) ----------------
__global__ __launch_bounds__(512) void k_pass6a(const float* __restrict__ og,
                                                const float* __restrict__ ob) {
    __shared__ double s_red[16 * 2];
    const int tid = threadIdx.x;
    double v2[2] = {0.0, 0.0};
    for (int jj = tid; jj < DFF; jj += 512) {
        const double x = g_v[jj];
        v2[0] += x; v2[1] += x * x;
    }
    block_reduce_d<2>(v2, s_red);
    const double mu = v2[0] * (1.0 / DFF);
    const double rs = 1.0 / sqrt(v2[1] * (1.0 / DFF) - mu * mu + EPSD);
    for (int jj = tid; jj < DFF; jj += 512)
        g_u[jj] = (g_v[jj] - mu) * rs * (double)og[jj] + (double)ob[jj];
}

// ---------------- kernel: final projection GEMV (fp64) ----------------
__global__ __launch_bounds__(128) void k_pass6b(const float* __restrict__ Wp,
                                                const float* __restrict__ bp,
                                                float* __restrict__ out) {
    __shared__ double s_red[4 * 1];
    const int d = blockIdx.x;
    const int tid = threadIdx.x;
    double acc[1] = {0.0};
    const float* wp = Wp + (size_t)d * DFF;
    for (int jj = tid; jj < DFF; jj += 128) acc[0] += g_u[jj] * (double)wp[jj];
    block_reduce_d<1>(acc, s_red);
    if (tid == 0) out[d] = (float)(acc[0] + (double)bp[d]);
}

// ---------------- launcher ----------------
extern "C" void kernel_launch(void* const* d_in, const int* in_sizes, int n_in,
                              void* d_out, int out_size) {
    const float* x      = (const float*)d_in[0];
    const float* Wg     = (const float*)d_in[1];
    const float* bgates = (const float*)d_in[2];
    // d_in[3] = Wr_gates: multiplies zero initial state -> unused
    const float* lng    = (const float*)d_in[4];
    const float* lnb    = (const float*)d_in[5];
    const float* lnoutg = (const float*)d_in[6];
    const float* lnoutb = (const float*)d_in[7];
    const float* Wl     = (const float*)d_in[8];
    const float* bl     = (const float*)d_in[9];
    const float* Wr     = (const float*)d_in[10];
    const float* br     = (const float*)d_in[11];
    const float* Wp     = (const float*)d_in[12];
    const float* bp     = (const float*)d_in[13];
    float* out = (float*)d_out;

    k_zero<<<8, 512>>>();
    k_silu<<<(MROWS * (size_t)DM) / (256 * 4), 256>>>(x);
    k_gemm_oz<<<dim3(64, 8, 8), 256>>>(Wg);   // gates o,z — R8 TF32 (proven)
    k_gemm_if<<<dim3(64, 8, 8), 256>>>(Wg);   // gates i,f — R8 scalar (proven)
    k_pass2<<<296, 512>>>(bgates, lng, lnb);
    k_redsum<<<DM / 32, 256>>>();             // smem-staged, bit-exact chains
    k_pass3<<<296, 512>>>(lng, lnb);
    k_pass4<<<1, 512>>>(lng, lnb);
    k_pass5<<<DFF, 128>>>(Wl, bl, Wr, br);
    k_pass6a<<<1, 512>>>(lnoutg, lnoutb);
    k_pass6b<<<DM, 128>>>(Wp, bp, out);
}